// round 1
// baseline (speedup 1.0000x reference)
#include <cuda_runtime.h>
#include <cstdint>

#define B2     2
#define CH     192
#define C3     (3*CH)
#define HEADS  4
#define HD     48
#define NSP    4096

#define BQ 64
#define BK 64
#define PTS 68   // padded row stride for Pt (16B-aligned: 68*4=272=17*16)

// ---------------- scratch (device globals; no allocation allowed) ----------------
__device__ float g_qkv [B2 * C3 * NSP];   // after 1x1 qkv conv
__device__ float g_qkv2[B2 * C3 * NSP];   // after depthwise conv (+bias); q,k normalized in-place
__device__ float g_att [B2 * CH * NSP];   // attention output before projection

// ---------------- 1x1 conv as GEMM: C[b,o,n] = sum_c A[b,c,n]*W[o,c] + bias[o] ----
// grid: (NSP/64, OC/64, B2), block 256, tile 64o x 64n, BK=16, 4x4 microtile
__global__ void __launch_bounds__(256) conv1x1_kernel(
    const float* __restrict__ A, const float* __restrict__ W,
    const float* __restrict__ bias, float* __restrict__ Cout,
    int OC, int IC)
{
    __shared__ __align__(16) float xs[16][64];
    __shared__ __align__(16) float ws[16][64];

    const int t  = threadIdx.x;
    const int tx = t & 15;        // n-group
    const int ty = t >> 4;        // o-group
    const int n0 = blockIdx.x * 64;
    const int o0 = blockIdx.y * 64;
    const int b  = blockIdx.z;

    const float* Ab = A + ((size_t)b * IC) * NSP + n0;

    float acc[4][4];
#pragma unroll
    for (int a = 0; a < 4; ++a)
#pragma unroll
        for (int c = 0; c < 4; ++c) acc[a][c] = 0.f;

    for (int c0 = 0; c0 < IC; c0 += 16) {
        // load x tile: 16 x 64 floats = 256 float4, exactly one per thread
        {
            int d  = t >> 4;
            int n4 = t & 15;
            *(float4*)&xs[d][n4 * 4] =
                *(const float4*)(Ab + (size_t)(c0 + d) * NSP + n4 * 4);
        }
        // load w tile (strided in global; small, L2-resident)
#pragma unroll
        for (int r = 0; r < 4; ++r) {
            int e  = t + r * 256;
            int kk = e >> 6;
            int o  = e & 63;
            ws[kk][o] = W[(size_t)(o0 + o) * IC + c0 + kk];
        }
        __syncthreads();

#pragma unroll
        for (int kk = 0; kk < 16; ++kk) {
            float4 w4 = *(const float4*)&ws[kk][ty * 4];
            float4 x4 = *(const float4*)&xs[kk][tx * 4];
            float wa[4] = {w4.x, w4.y, w4.z, w4.w};
            float xa[4] = {x4.x, x4.y, x4.z, x4.w};
#pragma unroll
            for (int a = 0; a < 4; ++a)
#pragma unroll
                for (int c = 0; c < 4; ++c)
                    acc[a][c] += wa[a] * xa[c];
        }
        __syncthreads();
    }

#pragma unroll
    for (int a = 0; a < 4; ++a) {
        int o = o0 + ty * 4 + a;
        float bv = bias[o];
        float4 v = make_float4(acc[a][0] + bv, acc[a][1] + bv,
                               acc[a][2] + bv, acc[a][3] + bv);
        *(float4*)(Cout + ((size_t)b * OC + o) * NSP + n0 + tx * 4) = v;
    }
}

// ---------------- 3x3 depthwise conv, pad 1 ----------------
// grid: (B2*C3, NSP/256), block 256
__global__ void __launch_bounds__(256) dwconv_kernel(
    const float* __restrict__ in, const float* __restrict__ wdw,
    const float* __restrict__ bias, float* __restrict__ out)
{
    const int bc = blockIdx.x;           // b*C3 + ch
    const int ch = bc % C3;
    const float* p = in + (size_t)bc * NSP;
    float*       q = out + (size_t)bc * NSP;

    float w9[9];
#pragma unroll
    for (int i = 0; i < 9; ++i) w9[i] = wdw[ch * 9 + i];

    const int idx = blockIdx.y * 256 + threadIdx.x;
    const int y = idx >> 6;
    const int x = idx & 63;

    float acc = bias[ch];
#pragma unroll
    for (int dy = -1; dy <= 1; ++dy) {
        int yy = y + dy;
        if (yy < 0 || yy > 63) continue;
#pragma unroll
        for (int dx = -1; dx <= 1; ++dx) {
            int xx = x + dx;
            if (xx < 0 || xx > 63) continue;
            acc += __ldg(p + yy * 64 + xx) * w9[(dy + 1) * 3 + (dx + 1)];
        }
    }
    q[idx] = acc;
}

// ---------------- per-(b,head,n) L2 norm of q and k; temperature folded into q ---
// grid: (B2*HEADS, NSP/256), block 256
__global__ void __launch_bounds__(256) norm_kernel(float* qkv, const float* __restrict__ temp)
{
    const int bh   = blockIdx.x;
    const int b    = bh >> 2;
    const int head = bh & 3;
    const int n    = blockIdx.y * 256 + threadIdx.x;

    float* qp = qkv + ((size_t)(b * C3) + head * HD) * NSP + n;
    float* kp = qp + (size_t)CH * NSP;

    float sq = 0.f, sk = 0.f;
#pragma unroll 16
    for (int d = 0; d < HD; ++d) {
        float qv = qp[(size_t)d * NSP]; sq += qv * qv;
        float kv = kp[(size_t)d * NSP]; sk += kv * kv;
    }
    const float qs = temp[head] / fmaxf(sqrtf(sq), 1e-12f);
    const float ks = 1.0f        / fmaxf(sqrtf(sk), 1e-12f);
#pragma unroll 16
    for (int d = 0; d < HD; ++d) {
        qp[(size_t)d * NSP] *= qs;
        kp[(size_t)d * NSP] *= ks;
    }
}

// ---------------- fused flash attention (fp32, online softmax) ----------------
// grid: (NSP/BQ, B2*HEADS), block 256
// Q,K,V layout: [d=48][n=4096] per (b,head), n contiguous.
// S stored transposed: Pt[j][i] so both GEMMs read along contiguous dims.
__global__ void __launch_bounds__(256) attn_kernel(
    const float* __restrict__ qkv, float* __restrict__ out)
{
    __shared__ __align__(16) float Qs[HD][BQ];    // 12 KB
    __shared__ __align__(16) float KVs[HD][BK];   // 12 KB (K, then reused for V)
    __shared__ __align__(16) float Pt[BK][PTS];   // 17 KB (S^T / P^T)
    __shared__ float m_s[BQ], l_s[BQ], al_s[BQ];

    const int t  = threadIdx.x;
    const int tx = t & 15;
    const int ty = t >> 4;
    const int bh = blockIdx.y;
    const int b  = bh >> 2;
    const int head = bh & 3;
    const int n0 = blockIdx.x * BQ;

    const float* qbase = qkv + ((size_t)(b * C3) + head * HD) * NSP;
    const float* kbase = qbase + (size_t)CH * NSP;
    const float* vbase = kbase + (size_t)CH * NSP;

    // load Q tile [48][64]
#pragma unroll
    for (int e = 0; e < 3; ++e) {
        int idx = t + e * 256;        // float4 index 0..767
        int d = idx >> 4, i4 = idx & 15;
        *(float4*)&Qs[d][i4 * 4] =
            *(const float4*)(qbase + (size_t)d * NSP + n0 + i4 * 4);
    }
    if (t < BQ) { m_s[t] = -1e30f; l_s[t] = 0.f; al_s[t] = 0.f; }

    float O[3][4];
#pragma unroll
    for (int r = 0; r < 3; ++r)
#pragma unroll
        for (int s = 0; s < 4; ++s) O[r][s] = 0.f;

    __syncthreads();

    const int row  = t >> 2;   // query row for softmax phase
    const int part = t & 3;    // column partition (j = part + 4s)
    const int i0   = tx * 4;
    const int d0   = ty * 3;

    for (int m0 = 0; m0 < NSP; m0 += BK) {
        // ---- phase 1: load K tile into KVs ----
#pragma unroll
        for (int e = 0; e < 3; ++e) {
            int idx = t + e * 256;
            int d = idx >> 4, j4 = idx & 15;
            *(float4*)&KVs[d][j4 * 4] =
                *(const float4*)(kbase + (size_t)d * NSP + m0 + j4 * 4);
        }
        __syncthreads();

        // ---- phase 2: S = Q^T K, write transposed to Pt ----
        float acc[4][4];
#pragma unroll
        for (int a = 0; a < 4; ++a)
#pragma unroll
            for (int c = 0; c < 4; ++c) acc[a][c] = 0.f;

#pragma unroll 8
        for (int d = 0; d < HD; ++d) {
            float4 q4 = *(const float4*)&Qs[d][ty * 4];
            float4 k4 = *(const float4*)&KVs[d][tx * 4];
            float qa[4] = {q4.x, q4.y, q4.z, q4.w};
            float ka[4] = {k4.x, k4.y, k4.z, k4.w};
#pragma unroll
            for (int a = 0; a < 4; ++a)
#pragma unroll
                for (int c = 0; c < 4; ++c)
                    acc[a][c] += qa[a] * ka[c];
        }
#pragma unroll
        for (int c = 0; c < 4; ++c) {
            *(float4*)&Pt[tx * 4 + c][ty * 4] =
                make_float4(acc[0][c], acc[1][c], acc[2][c], acc[3][c]);
        }
        __syncthreads();

        // ---- phase 3: load V tile into KVs (overlapped) + online softmax on Pt ----
#pragma unroll
        for (int e = 0; e < 3; ++e) {
            int idx = t + e * 256;
            int d = idx >> 4, j4 = idx & 15;
            *(float4*)&KVs[d][j4 * 4] =
                *(const float4*)(vbase + (size_t)d * NSP + m0 + j4 * 4);
        }
        {
            float vals[16];
            float mx = -1e30f;
#pragma unroll
            for (int s = 0; s < 16; ++s) {
                vals[s] = Pt[part + 4 * s][row];
                mx = fmaxf(mx, vals[s]);
            }
            mx = fmaxf(mx, __shfl_xor_sync(0xffffffffu, mx, 1));
            mx = fmaxf(mx, __shfl_xor_sync(0xffffffffu, mx, 2));
            float mold = m_s[row];
            float mnew = fmaxf(mold, mx);
            float sum = 0.f;
#pragma unroll
            for (int s = 0; s < 16; ++s) {
                float p = __expf(vals[s] - mnew);
                Pt[part + 4 * s][row] = p;
                sum += p;
            }
            sum += __shfl_xor_sync(0xffffffffu, sum, 1);
            sum += __shfl_xor_sync(0xffffffffu, sum, 2);
            if (part == 0) {
                float alpha = __expf(mold - mnew);
                l_s[row]  = l_s[row] * alpha + sum;
                m_s[row]  = mnew;
                al_s[row] = alpha;
            }
        }
        __syncthreads();

        // ---- phase 4: O[d][i] = O*alpha_i + V @ P^T ----
        {
            float a0 = al_s[i0], a1 = al_s[i0 + 1], a2 = al_s[i0 + 2], a3 = al_s[i0 + 3];
#pragma unroll
            for (int r = 0; r < 3; ++r) {
                O[r][0] *= a0; O[r][1] *= a1; O[r][2] *= a2; O[r][3] *= a3;
            }
#pragma unroll 4
            for (int j = 0; j < BK; ++j) {
                float v0 = KVs[d0][j];
                float v1 = KVs[d0 + 1][j];
                float v2 = KVs[d0 + 2][j];
                float4 p4 = *(const float4*)&Pt[j][i0];
                O[0][0] += v0 * p4.x; O[0][1] += v0 * p4.y; O[0][2] += v0 * p4.z; O[0][3] += v0 * p4.w;
                O[1][0] += v1 * p4.x; O[1][1] += v1 * p4.y; O[1][2] += v1 * p4.z; O[1][3] += v1 * p4.w;
                O[2][0] += v2 * p4.x; O[2][1] += v2 * p4.y; O[2][2] += v2 * p4.z; O[2][3] += v2 * p4.w;
            }
        }
        __syncthreads();
    }

    // ---- epilogue: divide by l, write [d][n] ----
    float il0 = 1.f / l_s[i0];
    float il1 = 1.f / l_s[i0 + 1];
    float il2 = 1.f / l_s[i0 + 2];
    float il3 = 1.f / l_s[i0 + 3];
#pragma unroll
    for (int r = 0; r < 3; ++r) {
        int d = d0 + r;
        float4 o4 = make_float4(O[r][0] * il0, O[r][1] * il1,
                                O[r][2] * il2, O[r][3] * il3);
        *(float4*)(out + ((size_t)(b * CH) + head * HD + d) * NSP + n0 + i0) = o4;
    }
}

// ---------------- launcher ----------------
extern "C" void kernel_launch(void* const* d_in, const int* in_sizes, int n_in,
                              void* d_out, int out_size)
{
    const float* x      = (const float*)d_in[0];
    const float* w_qkv  = (const float*)d_in[1];
    const float* b_qkv  = (const float*)d_in[2];
    const float* w_dw   = (const float*)d_in[3];
    const float* b_dw   = (const float*)d_in[4];
    const float* w_proj = (const float*)d_in[5];
    const float* b_proj = (const float*)d_in[6];
    const float* temp   = (const float*)d_in[7];
    float* out = (float*)d_out;

    float* qkv1; cudaGetSymbolAddress((void**)&qkv1, g_qkv);
    float* qkv2; cudaGetSymbolAddress((void**)&qkv2, g_qkv2);
    float* att;  cudaGetSymbolAddress((void**)&att,  g_att);

    // 1) qkv 1x1 conv: [B2, 576, 4096]
    conv1x1_kernel<<<dim3(NSP / 64, C3 / 64, B2), 256>>>(x, w_qkv, b_qkv, qkv1, C3, CH);
    // 2) 3x3 depthwise conv + bias
    dwconv_kernel<<<dim3(B2 * C3, NSP / 256), 256>>>(qkv1, w_dw, b_dw, qkv2);
    // 3) normalize q,k in-place (temperature folded into q)
    norm_kernel<<<dim3(B2 * HEADS, NSP / 256), 256>>>(qkv2, temp);
    // 4) flash attention
    attn_kernel<<<dim3(NSP / BQ, B2 * HEADS), 256>>>(qkv2, att);
    // 5) output projection
    conv1x1_kernel<<<dim3(NSP / 64, CH / 64, B2), 256>>>(att, w_proj, b_proj, out, CH, CH);
}

// round 2
// speedup vs baseline: 1.9328x; 1.9328x over previous
#include <cuda_runtime.h>
#include <cstdint>

#define B2     2
#define CH     192
#define C3     (3*CH)
#define HEADS  4
#define HD     48
#define NSP    4096

#define BQ 64
#define BK 64
#define QS_STRIDE 72   // 8 mod 32 -> (8d + i) bank bijection for A/B frag loads
#define KS_STRIDE 72
#define VS_STRIDE 68   // 4 mod 32 -> (4d + j) bank bijection
#define PS_STRIDE 68

// ---------------- scratch (device globals; no allocation allowed) ----------------
__device__ float g_qkv [B2 * C3 * NSP];
__device__ float g_qkv2[B2 * C3 * NSP];
__device__ float g_att [B2 * CH * NSP];

// ---------------- helpers ----------------
__device__ __forceinline__ uint32_t f2tf32(float f) {
    uint32_t u;
    asm("cvt.rna.tf32.f32 %0, %1;" : "=r"(u) : "f"(f));
    return u;
}

__device__ __forceinline__ void mma_tf32(float c[4],
                                         uint32_t a0, uint32_t a1, uint32_t a2, uint32_t a3,
                                         uint32_t b0, uint32_t b1) {
    asm volatile(
        "mma.sync.aligned.m16n8k8.row.col.f32.tf32.tf32.f32 "
        "{%0,%1,%2,%3}, {%4,%5,%6,%7}, {%8,%9}, {%0,%1,%2,%3};"
        : "+f"(c[0]), "+f"(c[1]), "+f"(c[2]), "+f"(c[3])
        : "r"(a0), "r"(a1), "r"(a2), "r"(a3), "r"(b0), "r"(b1));
}

// ---------------- 1x1 conv as GEMM (unchanged from R1) ----------------
__global__ void __launch_bounds__(256) conv1x1_kernel(
    const float* __restrict__ A, const float* __restrict__ W,
    const float* __restrict__ bias, float* __restrict__ Cout,
    int OC, int IC)
{
    __shared__ __align__(16) float xs[16][64];
    __shared__ __align__(16) float ws[16][64];

    const int t  = threadIdx.x;
    const int tx = t & 15;
    const int ty = t >> 4;
    const int n0 = blockIdx.x * 64;
    const int o0 = blockIdx.y * 64;
    const int b  = blockIdx.z;

    const float* Ab = A + ((size_t)b * IC) * NSP + n0;

    float acc[4][4];
#pragma unroll
    for (int a = 0; a < 4; ++a)
#pragma unroll
        for (int c = 0; c < 4; ++c) acc[a][c] = 0.f;

    for (int c0 = 0; c0 < IC; c0 += 16) {
        {
            int d  = t >> 4;
            int n4 = t & 15;
            *(float4*)&xs[d][n4 * 4] =
                *(const float4*)(Ab + (size_t)(c0 + d) * NSP + n4 * 4);
        }
#pragma unroll
        for (int r = 0; r < 4; ++r) {
            int e  = t + r * 256;
            int kk = e >> 6;
            int o  = e & 63;
            ws[kk][o] = W[(size_t)(o0 + o) * IC + c0 + kk];
        }
        __syncthreads();

#pragma unroll
        for (int kk = 0; kk < 16; ++kk) {
            float4 w4 = *(const float4*)&ws[kk][ty * 4];
            float4 x4 = *(const float4*)&xs[kk][tx * 4];
            float wa[4] = {w4.x, w4.y, w4.z, w4.w};
            float xa[4] = {x4.x, x4.y, x4.z, x4.w};
#pragma unroll
            for (int a = 0; a < 4; ++a)
#pragma unroll
                for (int c = 0; c < 4; ++c)
                    acc[a][c] += wa[a] * xa[c];
        }
        __syncthreads();
    }

#pragma unroll
    for (int a = 0; a < 4; ++a) {
        int o = o0 + ty * 4 + a;
        float bv = bias[o];
        float4 v = make_float4(acc[a][0] + bv, acc[a][1] + bv,
                               acc[a][2] + bv, acc[a][3] + bv);
        *(float4*)(Cout + ((size_t)b * OC + o) * NSP + n0 + tx * 4) = v;
    }
}

// ---------------- 3x3 depthwise conv, pad 1 (unchanged) ----------------
__global__ void __launch_bounds__(256) dwconv_kernel(
    const float* __restrict__ in, const float* __restrict__ wdw,
    const float* __restrict__ bias, float* __restrict__ out)
{
    const int bc = blockIdx.x;
    const int ch = bc % C3;
    const float* p = in + (size_t)bc * NSP;
    float*       q = out + (size_t)bc * NSP;

    float w9[9];
#pragma unroll
    for (int i = 0; i < 9; ++i) w9[i] = wdw[ch * 9 + i];

    const int idx = blockIdx.y * 256 + threadIdx.x;
    const int y = idx >> 6;
    const int x = idx & 63;

    float acc = bias[ch];
#pragma unroll
    for (int dy = -1; dy <= 1; ++dy) {
        int yy = y + dy;
        if (yy < 0 || yy > 63) continue;
#pragma unroll
        for (int dx = -1; dx <= 1; ++dx) {
            int xx = x + dx;
            if (xx < 0 || xx > 63) continue;
            acc += __ldg(p + yy * 64 + xx) * w9[(dy + 1) * 3 + (dx + 1)];
        }
    }
    q[idx] = acc;
}

// ---------------- per-(b,head,n) L2 norm (temperature folded into q) ----------------
__global__ void __launch_bounds__(256) norm_kernel(float* qkv, const float* __restrict__ temp)
{
    const int bh   = blockIdx.x;
    const int b    = bh >> 2;
    const int head = bh & 3;
    const int n    = blockIdx.y * 256 + threadIdx.x;

    float* qp = qkv + ((size_t)(b * C3) + head * HD) * NSP + n;
    float* kp = qp + (size_t)CH * NSP;

    float sq = 0.f, sk = 0.f;
#pragma unroll 16
    for (int d = 0; d < HD; ++d) {
        float qv = qp[(size_t)d * NSP]; sq += qv * qv;
        float kv = kp[(size_t)d * NSP]; sk += kv * kv;
    }
    const float qs = temp[head] / fmaxf(sqrtf(sq), 1e-12f);
    const float ks = 1.0f        / fmaxf(sqrtf(sk), 1e-12f);
#pragma unroll 16
    for (int d = 0; d < HD; ++d) {
        qp[(size_t)d * NSP] *= qs;
        kp[(size_t)d * NSP] *= ks;
    }
}

// ---------------- flash attention with tf32 mma.sync ----------------
// grid: (NSP/BQ, B2*HEADS), block 256 (8 warps)
// S warp layout: 4 (i16) x 2 (j32).  O warp layout: 4 (i16) x 2 (d24).
__global__ void __launch_bounds__(256) attn_kernel(
    const float* __restrict__ qkv, float* __restrict__ out)
{
    __shared__ __align__(16) float Qs[HD * QS_STRIDE];   // 13.5 KB (tf32 bits)
    __shared__ __align__(16) float KV[HD * KS_STRIDE];   // 13.5 KB (K stride 72 / V stride 68)
    __shared__ __align__(16) float Ps[BQ * PS_STRIDE];   // 17 KB (S / P / final O staging)
    __shared__ float m_s[BQ], l_s[BQ], al_s[BQ];

    const int t    = threadIdx.x;
    const int lane = t & 31;
    const int wid  = t >> 5;
    const int wi   = wid & 3;        // i block (16 rows)
    const int wj   = wid >> 2;       // j block for S (32 cols) / d block for O (24 dims)
    const int i0w  = wi * 16;
    const int r    = lane >> 2;      // 0..7
    const int cc   = lane & 3;       // 0..3

    const int bh   = blockIdx.y;
    const int b    = bh >> 2;
    const int head = bh & 3;
    const int n0   = blockIdx.x * BQ;

    const float* qbase = qkv + ((size_t)(b * C3) + head * HD) * NSP;
    const float* kbase = qbase + (size_t)CH * NSP;
    const float* vbase = kbase + (size_t)CH * NSP;

    // load Q tile [48][64] -> Qs (tf32), stride 72
#pragma unroll
    for (int e = 0; e < 3; ++e) {
        int idx = t + e * 256;           // float4 index 0..767
        int d = idx >> 4, i4 = (idx & 15) * 4;
        float4 v = *(const float4*)(qbase + (size_t)d * NSP + n0 + i4);
        uint4 u = make_uint4(f2tf32(v.x), f2tf32(v.y), f2tf32(v.z), f2tf32(v.w));
        *(uint4*)&Qs[d * QS_STRIDE + i4] = u;
    }
    if (t < BQ) { m_s[t] = -1e30f; l_s[t] = 0.f; al_s[t] = 0.f; }

    float oacc[3][4];
#pragma unroll
    for (int nt = 0; nt < 3; ++nt)
#pragma unroll
        for (int e = 0; e < 4; ++e) oacc[nt][e] = 0.f;

    __syncthreads();

    const int row  = t >> 2;   // softmax row
    const int part = t & 3;    // softmax column partition (16 cols each)

    for (int m0 = 0; m0 < NSP; m0 += BK) {
        // ---- load K tile -> KV (stride 72, tf32) ----
#pragma unroll
        for (int e = 0; e < 3; ++e) {
            int idx = t + e * 256;
            int d = idx >> 4, j4 = (idx & 15) * 4;
            float4 v = *(const float4*)(kbase + (size_t)d * NSP + m0 + j4);
            uint4 u = make_uint4(f2tf32(v.x), f2tf32(v.y), f2tf32(v.z), f2tf32(v.w));
            *(uint4*)&KV[d * KS_STRIDE + j4] = u;
        }
        __syncthreads();

        // ---- S = Q^T K  (warp tile 16i x 32j) ----
        float sacc[4][4];
#pragma unroll
        for (int nt = 0; nt < 4; ++nt)
#pragma unroll
            for (int e = 0; e < 4; ++e) sacc[nt][e] = 0.f;

        const int j0w = wj * 32;
#pragma unroll
        for (int ks = 0; ks < 6; ++ks) {
            const float* qk = &Qs[(ks * 8 + cc) * QS_STRIDE + i0w + r];
            uint32_t a0 = __float_as_uint(qk[0]);
            uint32_t a1 = __float_as_uint(qk[8]);
            uint32_t a2 = __float_as_uint(qk[4 * QS_STRIDE]);
            uint32_t a3 = __float_as_uint(qk[4 * QS_STRIDE + 8]);
#pragma unroll
            for (int nt = 0; nt < 4; ++nt) {
                const float* kk = &KV[(ks * 8 + cc) * KS_STRIDE + j0w + nt * 8 + r];
                uint32_t b0 = __float_as_uint(kk[0]);
                uint32_t b1 = __float_as_uint(kk[4 * KS_STRIDE]);
                mma_tf32(sacc[nt], a0, a1, a2, a3, b0, b1);
            }
        }
        __syncthreads();   // K reads done (V reuses buffer); prev-tile P reads done

        // ---- store S -> Ps (row-major, stride 68), and load V tile -> KV (stride 68) ----
#pragma unroll
        for (int nt = 0; nt < 4; ++nt) {
            int col = j0w + nt * 8 + 2 * cc;
            float* p0 = &Ps[(i0w + r) * PS_STRIDE + col];
            p0[0] = sacc[nt][0];
            p0[1] = sacc[nt][1];
            float* p1 = p0 + 8 * PS_STRIDE;
            p1[0] = sacc[nt][2];
            p1[1] = sacc[nt][3];
        }
#pragma unroll
        for (int e = 0; e < 3; ++e) {
            int idx = t + e * 256;
            int d = idx >> 4, j4 = (idx & 15) * 4;
            float4 v = *(const float4*)(vbase + (size_t)d * NSP + m0 + j4);
            uint4 u = make_uint4(f2tf32(v.x), f2tf32(v.y), f2tf32(v.z), f2tf32(v.w));
            *(uint4*)&KV[d * VS_STRIDE + j4] = u;
        }
        __syncthreads();

        // ---- online softmax on Ps rows ----
        {
            float vals[16];
            float mx = -1e30f;
            const float* pr = &Ps[row * PS_STRIDE + part * 16];
#pragma unroll
            for (int q4 = 0; q4 < 4; ++q4) {
                float4 v = *(const float4*)(pr + q4 * 4);
                vals[q4 * 4 + 0] = v.x; vals[q4 * 4 + 1] = v.y;
                vals[q4 * 4 + 2] = v.z; vals[q4 * 4 + 3] = v.w;
                mx = fmaxf(mx, fmaxf(fmaxf(v.x, v.y), fmaxf(v.z, v.w)));
            }
            mx = fmaxf(mx, __shfl_xor_sync(0xffffffffu, mx, 1));
            mx = fmaxf(mx, __shfl_xor_sync(0xffffffffu, mx, 2));
            float mold = m_s[row];
            float mnew = fmaxf(mold, mx);
            float sum = 0.f;
            float* pw = &Ps[row * PS_STRIDE + part * 16];
#pragma unroll
            for (int q4 = 0; q4 < 4; ++q4) {
                float p0 = __expf(vals[q4 * 4 + 0] - mnew);
                float p1 = __expf(vals[q4 * 4 + 1] - mnew);
                float p2 = __expf(vals[q4 * 4 + 2] - mnew);
                float p3 = __expf(vals[q4 * 4 + 3] - mnew);
                sum += (p0 + p1) + (p2 + p3);
                uint4 u = make_uint4(f2tf32(p0), f2tf32(p1), f2tf32(p2), f2tf32(p3));
                *(uint4*)(pw + q4 * 4) = u;
            }
            sum += __shfl_xor_sync(0xffffffffu, sum, 1);
            sum += __shfl_xor_sync(0xffffffffu, sum, 2);
            if (part == 0) {
                float alpha = __expf(mold - mnew);
                l_s[row]  = l_s[row] * alpha + sum;
                m_s[row]  = mnew;
                al_s[row] = alpha;
            }
        }
        __syncthreads();

        // ---- O = O*alpha + P V^T  (warp tile 16i x 24d) ----
        {
            float a_lo = al_s[i0w + r];
            float a_hi = al_s[i0w + r + 8];
            const int d0w = wj * 24;
#pragma unroll
            for (int nt = 0; nt < 3; ++nt) {
                oacc[nt][0] *= a_lo; oacc[nt][1] *= a_lo;
                oacc[nt][2] *= a_hi; oacc[nt][3] *= a_hi;
            }
#pragma unroll
            for (int ks = 0; ks < 8; ++ks) {
                const float* pk = &Ps[(i0w + r) * PS_STRIDE + ks * 8 + cc];
                uint32_t a0 = __float_as_uint(pk[0]);
                uint32_t a1 = __float_as_uint(pk[8 * PS_STRIDE]);
                uint32_t a2 = __float_as_uint(pk[4]);
                uint32_t a3 = __float_as_uint(pk[8 * PS_STRIDE + 4]);
#pragma unroll
                for (int nt = 0; nt < 3; ++nt) {
                    const float* vk = &KV[(d0w + nt * 8 + r) * VS_STRIDE + ks * 8 + cc];
                    uint32_t b0 = __float_as_uint(vk[0]);
                    uint32_t b1 = __float_as_uint(vk[4]);
                    mma_tf32(oacc[nt], a0, a1, a2, a3, b0, b1);
                }
            }
        }
        __syncthreads();
    }

    // ---- epilogue: scale by 1/l, stage transposed in Ps, coalesced store ----
    {
        float il_lo = 1.f / l_s[i0w + r];
        float il_hi = 1.f / l_s[i0w + r + 8];
        const int d0w = wj * 24;
#pragma unroll
        for (int nt = 0; nt < 3; ++nt) {
            int d = d0w + nt * 8 + 2 * cc;
            Ps[d * PS_STRIDE + i0w + r]           = oacc[nt][0] * il_lo;
            Ps[(d + 1) * PS_STRIDE + i0w + r]     = oacc[nt][1] * il_lo;
            Ps[d * PS_STRIDE + i0w + r + 8]       = oacc[nt][2] * il_hi;
            Ps[(d + 1) * PS_STRIDE + i0w + r + 8] = oacc[nt][3] * il_hi;
        }
    }
    __syncthreads();
    float* obase = out + ((size_t)(b * CH) + head * HD) * NSP + n0;
#pragma unroll
    for (int e = 0; e < 3; ++e) {
        int idx = t + e * 256;
        int d = idx >> 4, i4 = (idx & 15) * 4;
        float4 v = *(const float4*)&Ps[d * PS_STRIDE + i4];
        *(float4*)(obase + (size_t)d * NSP + i4) = v;
    }
}

// ---------------- launcher ----------------
extern "C" void kernel_launch(void* const* d_in, const int* in_sizes, int n_in,
                              void* d_out, int out_size)
{
    const float* x      = (const float*)d_in[0];
    const float* w_qkv  = (const float*)d_in[1];
    const float* b_qkv  = (const float*)d_in[2];
    const float* w_dw   = (const float*)d_in[3];
    const float* b_dw   = (const float*)d_in[4];
    const float* w_proj = (const float*)d_in[5];
    const float* b_proj = (const float*)d_in[6];
    const float* temp   = (const float*)d_in[7];
    float* out = (float*)d_out;

    float* qkv1; cudaGetSymbolAddress((void**)&qkv1, g_qkv);
    float* qkv2; cudaGetSymbolAddress((void**)&qkv2, g_qkv2);
    float* att;  cudaGetSymbolAddress((void**)&att,  g_att);

    conv1x1_kernel<<<dim3(NSP / 64, C3 / 64, B2), 256>>>(x, w_qkv, b_qkv, qkv1, C3, CH);
    dwconv_kernel<<<dim3(B2 * C3, NSP / 256), 256>>>(qkv1, w_dw, b_dw, qkv2);
    norm_kernel<<<dim3(B2 * HEADS, NSP / 256), 256>>>(qkv2, temp);
    attn_kernel<<<dim3(NSP / BQ, B2 * HEADS), 256>>>(qkv2, att);
    conv1x1_kernel<<<dim3(NSP / 64, CH / 64, B2), 256>>>(att, w_proj, b_proj, out, CH, CH);
}

// round 3
// speedup vs baseline: 3.5730x; 1.8486x over previous
#include <cuda_runtime.h>
#include <cuda_fp16.h>
#include <cstdint>

#define B2     2
#define CH     192
#define C3     (3*CH)
#define HEADS  4
#define HD     48
#define NSP    4096
#define L2E    1.44269504f

#define QKSTR 56   // half stride: 112B = 7 16B-chunks (odd) -> ldmatrix conflict-free
#define VSTR  72   // 144B = 9 chunks (odd)

// ---------------- scratch ----------------
__device__ float g_qkv [B2 * C3 * NSP];
__device__ float g_qkv2[B2 * C3 * NSP];
__device__ float g_att [B2 * CH * NSP];

// ---------------- asm helpers ----------------
__device__ __forceinline__ uint32_t sptr(const void* p) {
    return (uint32_t)__cvta_generic_to_shared(p);
}
__device__ __forceinline__ void ldsm_x4(uint32_t& r0, uint32_t& r1, uint32_t& r2, uint32_t& r3,
                                        const __half* p) {
    asm volatile("ldmatrix.sync.aligned.m8n8.x4.shared.b16 {%0,%1,%2,%3}, [%4];"
                 : "=r"(r0), "=r"(r1), "=r"(r2), "=r"(r3) : "r"(sptr(p)));
}
__device__ __forceinline__ void mma16816(float c[4],
                                         uint32_t a0, uint32_t a1, uint32_t a2, uint32_t a3,
                                         uint32_t b0, uint32_t b1) {
    asm volatile(
        "mma.sync.aligned.m16n8k16.row.col.f32.f16.f16.f32 "
        "{%0,%1,%2,%3}, {%4,%5,%6,%7}, {%8,%9}, {%0,%1,%2,%3};"
        : "+f"(c[0]), "+f"(c[1]), "+f"(c[2]), "+f"(c[3])
        : "r"(a0), "r"(a1), "r"(a2), "r"(a3), "r"(b0), "r"(b1));
}
// pack two f32 -> f16x2 (lo = second arg)
__device__ __forceinline__ uint32_t cvt2(float hi, float lo) {
    uint32_t r;
    asm("cvt.rn.f16x2.f32 %0, %1, %2;" : "=r"(r) : "f"(hi), "f"(lo));
    return r;
}
__device__ __forceinline__ uint32_t ex2h2(uint32_t x) {
    uint32_t r;
    asm("ex2.approx.f16x2 %0, %1;" : "=r"(r) : "r"(x));
    return r;
}
__device__ __forceinline__ uint32_t hadd2(uint32_t a, uint32_t b) {
    uint32_t r;
    asm("add.rn.f16x2 %0, %1, %2;" : "=r"(r) : "r"(a), "r"(b));
    return r;
}
__device__ __forceinline__ float2 h22f2(uint32_t u) {
    __half2 h = *reinterpret_cast<__half2*>(&u);
    return __half22float2(h);
}

// ---------------- 1x1 conv as GEMM (unchanged) ----------------
__global__ void __launch_bounds__(256) conv1x1_kernel(
    const float* __restrict__ A, const float* __restrict__ W,
    const float* __restrict__ bias, float* __restrict__ Cout,
    int OC, int IC)
{
    __shared__ __align__(16) float xs[16][64];
    __shared__ __align__(16) float ws[16][64];

    const int t  = threadIdx.x;
    const int tx = t & 15;
    const int ty = t >> 4;
    const int n0 = blockIdx.x * 64;
    const int o0 = blockIdx.y * 64;
    const int b  = blockIdx.z;

    const float* Ab = A + ((size_t)b * IC) * NSP + n0;

    float acc[4][4];
#pragma unroll
    for (int a = 0; a < 4; ++a)
#pragma unroll
        for (int c = 0; c < 4; ++c) acc[a][c] = 0.f;

    for (int c0 = 0; c0 < IC; c0 += 16) {
        {
            int d  = t >> 4;
            int n4 = t & 15;
            *(float4*)&xs[d][n4 * 4] =
                *(const float4*)(Ab + (size_t)(c0 + d) * NSP + n4 * 4);
        }
#pragma unroll
        for (int r = 0; r < 4; ++r) {
            int e  = t + r * 256;
            int kk = e >> 6;
            int o  = e & 63;
            ws[kk][o] = W[(size_t)(o0 + o) * IC + c0 + kk];
        }
        __syncthreads();

#pragma unroll
        for (int kk = 0; kk < 16; ++kk) {
            float4 w4 = *(const float4*)&ws[kk][ty * 4];
            float4 x4 = *(const float4*)&xs[kk][tx * 4];
            float wa[4] = {w4.x, w4.y, w4.z, w4.w};
            float xa[4] = {x4.x, x4.y, x4.z, x4.w};
#pragma unroll
            for (int a = 0; a < 4; ++a)
#pragma unroll
                for (int c = 0; c < 4; ++c)
                    acc[a][c] += wa[a] * xa[c];
        }
        __syncthreads();
    }

#pragma unroll
    for (int a = 0; a < 4; ++a) {
        int o = o0 + ty * 4 + a;
        float bv = bias[o];
        float4 v = make_float4(acc[a][0] + bv, acc[a][1] + bv,
                               acc[a][2] + bv, acc[a][3] + bv);
        *(float4*)(Cout + ((size_t)b * OC + o) * NSP + n0 + tx * 4) = v;
    }
}

// ---------------- 3x3 depthwise conv (unchanged) ----------------
__global__ void __launch_bounds__(256) dwconv_kernel(
    const float* __restrict__ in, const float* __restrict__ wdw,
    const float* __restrict__ bias, float* __restrict__ out)
{
    const int bc = blockIdx.x;
    const int ch = bc % C3;
    const float* p = in + (size_t)bc * NSP;
    float*       q = out + (size_t)bc * NSP;

    float w9[9];
#pragma unroll
    for (int i = 0; i < 9; ++i) w9[i] = wdw[ch * 9 + i];

    const int idx = blockIdx.y * 256 + threadIdx.x;
    const int y = idx >> 6;
    const int x = idx & 63;

    float acc = bias[ch];
#pragma unroll
    for (int dy = -1; dy <= 1; ++dy) {
        int yy = y + dy;
        if (yy < 0 || yy > 63) continue;
#pragma unroll
        for (int dx = -1; dx <= 1; ++dx) {
            int xx = x + dx;
            if (xx < 0 || xx > 63) continue;
            acc += __ldg(p + yy * 64 + xx) * w9[(dy + 1) * 3 + (dx + 1)];
        }
    }
    q[idx] = acc;
}

// ---------------- L2 norm; q scaled by T*log2e (exp2 domain) ----------------
__global__ void __launch_bounds__(256) norm_kernel(float* qkv, const float* __restrict__ temp)
{
    const int bh   = blockIdx.x;
    const int b    = bh >> 2;
    const int head = bh & 3;
    const int n    = blockIdx.y * 256 + threadIdx.x;

    float* qp = qkv + ((size_t)(b * C3) + head * HD) * NSP + n;
    float* kp = qp + (size_t)CH * NSP;

    float sq = 0.f, sk = 0.f;
#pragma unroll 16
    for (int d = 0; d < HD; ++d) {
        float qv = qp[(size_t)d * NSP]; sq += qv * qv;
        float kv = kp[(size_t)d * NSP]; sk += kv * kv;
    }
    const float qs = (temp[head] * L2E) / fmaxf(sqrtf(sq), 1e-12f);
    const float ks = 1.0f / fmaxf(sqrtf(sk), 1e-12f);
#pragma unroll 16
    for (int d = 0; d < HD; ++d) {
        qp[(size_t)d * NSP] *= qs;
        kp[(size_t)d * NSP] *= ks;
    }
}

// ---------------- flash attention, fp16 mma + ldmatrix, register softmax ----------------
// grid: (64, 8), block 256 (8 warps). warp (wi = wid&3 -> 16 i rows, wj = wid>>2 -> 32 j cols)
// Each warp accumulates O[16i x 48d] PARTIAL over its j-half; wj pair reduced in epilogue.
__global__ void __launch_bounds__(256) attn_kernel(
    const float* __restrict__ qkv, const float* __restrict__ temp, float* __restrict__ out)
{
    __shared__ __align__(16) __half Qs[64 * QKSTR];        // 7  KB
    __shared__ __align__(16) __half Ks[2][64 * QKSTR];     // 14 KB
    __shared__ __align__(16) __half Vs[2][HD * VSTR];      // 13.5 KB
    __shared__ float lred[128];

    const int t    = threadIdx.x;
    const int lane = t & 31;
    const int wid  = t >> 5;
    const int wi   = wid & 3;
    const int wj   = wid >> 2;
    const int i0   = wi * 16;
    const int r    = lane >> 2;
    const int cc   = lane & 3;

    const int bh   = blockIdx.y;
    const int b    = bh >> 2;
    const int head = bh & 3;
    const int n0   = blockIdx.x * 64;

    const float* qbase = qkv + ((size_t)(b * C3) + head * HD) * NSP;
    const float* kbase = qbase + (size_t)CH * NSP;
    const float* vbase = kbase + (size_t)CH * NSP;
    const float  cbias = fabsf(temp[head]) * L2E;

    // per-thread load geometry
    const int jK = t & 63;          // K/Q: column (j or i), transpose store
    const int dg = (t >> 6) * 4;    // K/Q: d group base

    // ---- load Q (transpose [i][d]) ----
#pragma unroll
    for (int e = 0; e < 3; ++e) {
        int d0 = dg + e * 16;
        float f0 = qbase[(size_t)(d0 + 0) * NSP + n0 + jK];
        float f1 = qbase[(size_t)(d0 + 1) * NSP + n0 + jK];
        float f2 = qbase[(size_t)(d0 + 2) * NSP + n0 + jK];
        float f3 = qbase[(size_t)(d0 + 3) * NSP + n0 + jK];
        *(uint2*)&Qs[jK * QKSTR + d0] = make_uint2(cvt2(f1, f0), cvt2(f3, f2));
    }
    // ---- load K,V tile 0 into buffer 0 ----
#pragma unroll
    for (int e = 0; e < 3; ++e) {
        int d0 = dg + e * 16;
        float f0 = kbase[(size_t)(d0 + 0) * NSP + jK];
        float f1 = kbase[(size_t)(d0 + 1) * NSP + jK];
        float f2 = kbase[(size_t)(d0 + 2) * NSP + jK];
        float f3 = kbase[(size_t)(d0 + 3) * NSP + jK];
        *(uint2*)&Ks[0][jK * QKSTR + d0] = make_uint2(cvt2(f1, f0), cvt2(f3, f2));
    }
#pragma unroll
    for (int e = 0; e < 3; ++e) {
        int lin = t + e * 256;
        int dv = lin >> 4, j4 = (lin & 15) * 4;
        float4 v = *(const float4*)(vbase + (size_t)dv * NSP + j4);
        *(uint2*)&Vs[0][dv * VSTR + j4] = make_uint2(cvt2(v.y, v.x), cvt2(v.w, v.z));
    }

    float oacc[6][4];
#pragma unroll
    for (int nt = 0; nt < 6; ++nt)
#pragma unroll
        for (int e = 0; e < 4; ++e) oacc[nt][e] = 0.f;
    float l_lo = 0.f, l_hi = 0.f;

    __syncthreads();

    for (int it = 0; it < NSP / 64; ++it) {
        const int cur = it & 1;
        const __half* Kc = Ks[cur];
        const __half* Vc = Vs[cur];
        const bool has_next = (it < NSP / 64 - 1);
        const int m0n = (it + 1) * 64;

        // ---- prefetch next K,V tile into registers ----
        float kf[3][4];
        float4 vf[3];
        if (has_next) {
#pragma unroll
            for (int e = 0; e < 3; ++e) {
                int d0 = dg + e * 16;
                kf[e][0] = kbase[(size_t)(d0 + 0) * NSP + m0n + jK];
                kf[e][1] = kbase[(size_t)(d0 + 1) * NSP + m0n + jK];
                kf[e][2] = kbase[(size_t)(d0 + 2) * NSP + m0n + jK];
                kf[e][3] = kbase[(size_t)(d0 + 3) * NSP + m0n + jK];
            }
#pragma unroll
            for (int e = 0; e < 3; ++e) {
                int lin = t + e * 256;
                int dv = lin >> 4, j4 = (lin & 15) * 4;
                vf[e] = *(const float4*)(vbase + (size_t)dv * NSP + m0n + j4);
            }
        }

        // ---- S = Q K^T (warp: 16i x 32j) ----
        float sacc[4][4];
#pragma unroll
        for (int nt = 0; nt < 4; ++nt)
#pragma unroll
            for (int e = 0; e < 4; ++e) sacc[nt][e] = 0.f;

#pragma unroll
        for (int ks = 0; ks < 3; ++ks) {
            uint32_t a0, a1, a2, a3;
            ldsm_x4(a0, a1, a2, a3,
                    &Qs[(i0 + (lane & 15)) * QKSTR + ks * 16 + ((lane >> 4) << 3)]);
#pragma unroll
            for (int p = 0; p < 2; ++p) {
                uint32_t b0, b1, b2, b3;
                int row = wj * 32 + p * 16 + ((lane >> 4) << 3) + (lane & 7);
                int col = ks * 16 + (lane & 8);
                ldsm_x4(b0, b1, b2, b3, &Kc[row * QKSTR + col]);
                mma16816(sacc[2 * p],     a0, a1, a2, a3, b0, b1);
                mma16816(sacc[2 * p + 1], a0, a1, a2, a3, b2, b3);
            }
        }

        // ---- softmax in registers: P = exp2(S - c), fp16x2 ----
        uint32_t plo[4], phi[4];
        uint32_t sum_lo = 0, sum_hi = 0;
#pragma unroll
        for (int nt = 0; nt < 4; ++nt) {
            plo[nt] = ex2h2(cvt2(sacc[nt][1] - cbias, sacc[nt][0] - cbias));
            phi[nt] = ex2h2(cvt2(sacc[nt][3] - cbias, sacc[nt][2] - cbias));
            sum_lo = hadd2(sum_lo, plo[nt]);
            sum_hi = hadd2(sum_hi, phi[nt]);
        }
        {
            float2 f0 = h22f2(sum_lo); l_lo += f0.x + f0.y;
            float2 f1 = h22f2(sum_hi); l_hi += f1.x + f1.y;
        }

        // ---- O += P V^T (warp: 16i x 48d, partial over its 32 j) ----
#pragma unroll
        for (int nt = 0; nt < 6; ++nt) {
            uint32_t b0, b1, b2, b3;
            ldsm_x4(b0, b1, b2, b3,
                    &Vc[(nt * 8 + (lane & 7)) * VSTR + wj * 32 + ((lane >> 3) & 3) * 8]);
            mma16816(oacc[nt], plo[0], phi[0], plo[1], phi[1], b0, b1);
            mma16816(oacc[nt], plo[2], phi[2], plo[3], phi[3], b2, b3);
        }

        // ---- store prefetched tile to alternate buffer ----
        if (has_next) {
            const int nb = cur ^ 1;
#pragma unroll
            for (int e = 0; e < 3; ++e) {
                int d0 = dg + e * 16;
                *(uint2*)&Ks[nb][jK * QKSTR + d0] =
                    make_uint2(cvt2(kf[e][1], kf[e][0]), cvt2(kf[e][3], kf[e][2]));
            }
#pragma unroll
            for (int e = 0; e < 3; ++e) {
                int lin = t + e * 256;
                int dv = lin >> 4, j4 = (lin & 15) * 4;
                *(uint2*)&Vs[nb][dv * VSTR + j4] =
                    make_uint2(cvt2(vf[e].y, vf[e].x), cvt2(vf[e].w, vf[e].z));
            }
        }
        __syncthreads();
    }

    // ---- epilogue: reduce l (cc quad), exchange O across wj, scale, store ----
    l_lo += __shfl_xor_sync(0xffffffffu, l_lo, 1);
    l_lo += __shfl_xor_sync(0xffffffffu, l_lo, 2);
    l_hi += __shfl_xor_sync(0xffffffffu, l_hi, 1);
    l_hi += __shfl_xor_sync(0xffffffffu, l_hi, 2);
    if (cc == 0) {
        lred[wj * 64 + i0 + r]     = l_lo;
        lred[wj * 64 + i0 + r + 8] = l_hi;
    }
    float* Ored = (float*)&Ks[0][0];   // 64*48*4 = 12288B, fits in Ks region
    if (wj == 1) {
#pragma unroll
        for (int nt = 0; nt < 6; ++nt) {
            int d = nt * 8 + 2 * cc;
            Ored[(i0 + r) * 48 + d]         = oacc[nt][0];
            Ored[(i0 + r) * 48 + d + 1]     = oacc[nt][1];
            Ored[(i0 + r + 8) * 48 + d]     = oacc[nt][2];
            Ored[(i0 + r + 8) * 48 + d + 1] = oacc[nt][3];
        }
    }
    __syncthreads();
    if (wj == 0) {
        float linv_lo = 1.f / (lred[i0 + r]     + lred[64 + i0 + r]);
        float linv_hi = 1.f / (lred[i0 + r + 8] + lred[64 + i0 + r + 8]);
        float* ob = out + ((size_t)(b * CH) + head * HD) * NSP + n0;
#pragma unroll
        for (int nt = 0; nt < 6; ++nt) {
            int d = nt * 8 + 2 * cc;
            ob[(size_t)d * NSP + i0 + r]           = (oacc[nt][0] + Ored[(i0 + r) * 48 + d])         * linv_lo;
            ob[(size_t)(d + 1) * NSP + i0 + r]     = (oacc[nt][1] + Ored[(i0 + r) * 48 + d + 1])     * linv_lo;
            ob[(size_t)d * NSP + i0 + r + 8]       = (oacc[nt][2] + Ored[(i0 + r + 8) * 48 + d])     * linv_hi;
            ob[(size_t)(d + 1) * NSP + i0 + r + 8] = (oacc[nt][3] + Ored[(i0 + r + 8) * 48 + d + 1]) * linv_hi;
        }
    }
}

// ---------------- launcher ----------------
extern "C" void kernel_launch(void* const* d_in, const int* in_sizes, int n_in,
                              void* d_out, int out_size)
{
    const float* x      = (const float*)d_in[0];
    const float* w_qkv  = (const float*)d_in[1];
    const float* b_qkv  = (const float*)d_in[2];
    const float* w_dw   = (const float*)d_in[3];
    const float* b_dw   = (const float*)d_in[4];
    const float* w_proj = (const float*)d_in[5];
    const float* b_proj = (const float*)d_in[6];
    const float* temp   = (const float*)d_in[7];
    float* out = (float*)d_out;

    float* qkv1; cudaGetSymbolAddress((void**)&qkv1, g_qkv);
    float* qkv2; cudaGetSymbolAddress((void**)&qkv2, g_qkv2);
    float* att;  cudaGetSymbolAddress((void**)&att,  g_att);

    conv1x1_kernel<<<dim3(NSP / 64, C3 / 64, B2), 256>>>(x, w_qkv, b_qkv, qkv1, C3, CH);
    dwconv_kernel<<<dim3(B2 * C3, NSP / 256), 256>>>(qkv1, w_dw, b_dw, qkv2);
    norm_kernel<<<dim3(B2 * HEADS, NSP / 256), 256>>>(qkv2, temp);
    attn_kernel<<<dim3(NSP / 64, B2 * HEADS), 256>>>(qkv2, temp, att);
    conv1x1_kernel<<<dim3(NSP / 64, CH / 64, B2), 256>>>(att, w_proj, b_proj, out, CH, CH);
}

// round 4
// speedup vs baseline: 5.2745x; 1.4762x over previous
#include <cuda_runtime.h>
#include <cuda_fp16.h>
#include <cstdint>

#define B2     2
#define CH     192
#define C3     (3*CH)
#define HEADS  4
#define HD     48
#define NSP    4096
#define L2E    1.44269504f

#define QKSTR 56   // half stride: 7 16B-chunks (odd mod 8) -> ldmatrix conflict-free
#define VSTR  72   // 9 chunks
#define CSTR  40   // conv tiles: 5 chunks

// ---------------- scratch ----------------
__device__ float g_qkv [B2 * C3 * NSP];
__device__ float g_qkv2[B2 * C3 * NSP];
__device__ float g_att [B2 * CH * NSP];

// ---------------- asm helpers ----------------
__device__ __forceinline__ uint32_t sptr(const void* p) {
    return (uint32_t)__cvta_generic_to_shared(p);
}
__device__ __forceinline__ void ldsm_x4(uint32_t& r0, uint32_t& r1, uint32_t& r2, uint32_t& r3,
                                        const __half* p) {
    asm volatile("ldmatrix.sync.aligned.m8n8.x4.shared.b16 {%0,%1,%2,%3}, [%4];"
                 : "=r"(r0), "=r"(r1), "=r"(r2), "=r"(r3) : "r"(sptr(p)));
}
__device__ __forceinline__ void mma16816(float c[4],
                                         uint32_t a0, uint32_t a1, uint32_t a2, uint32_t a3,
                                         uint32_t b0, uint32_t b1) {
    asm volatile(
        "mma.sync.aligned.m16n8k16.row.col.f32.f16.f16.f32 "
        "{%0,%1,%2,%3}, {%4,%5,%6,%7}, {%8,%9}, {%0,%1,%2,%3};"
        : "+f"(c[0]), "+f"(c[1]), "+f"(c[2]), "+f"(c[3])
        : "r"(a0), "r"(a1), "r"(a2), "r"(a3), "r"(b0), "r"(b1));
}
__device__ __forceinline__ uint32_t cvt2(float hi, float lo) {
    uint32_t r;
    asm("cvt.rn.f16x2.f32 %0, %1, %2;" : "=r"(r) : "f"(hi), "f"(lo));
    return r;
}
__device__ __forceinline__ uint32_t ex2h2(uint32_t x) {
    uint32_t r;
    asm("ex2.approx.f16x2 %0, %1;" : "=r"(r) : "r"(x));
    return r;
}
__device__ __forceinline__ uint32_t hadd2(uint32_t a, uint32_t b) {
    uint32_t r;
    asm("add.rn.f16x2 %0, %1, %2;" : "=r"(r) : "r"(a), "r"(b));
    return r;
}
__device__ __forceinline__ float2 h22f2(uint32_t u) {
    __half2 h = *reinterpret_cast<__half2*>(&u);
    return __half22float2(h);
}
// split a float4 into hi (f16x2 pair) and lo residual (f16x2 pair)
__device__ __forceinline__ void split4(float4 f, uint2& hi, uint2& lo) {
    hi = make_uint2(cvt2(f.y, f.x), cvt2(f.w, f.z));
    float2 g0 = h22f2(hi.x), g1 = h22f2(hi.y);
    lo = make_uint2(cvt2(f.y - g0.y, f.x - g0.x), cvt2(f.w - g1.y, f.z - g1.x));
}

// ---------------- 1x1 conv as split-fp16 tensor GEMM ----------------
// C[b,o,n] = sum_c W[o,c] X[b,c,n] + bias[o]
// grid (NSP/64, OC/64, B2), block 256 (8 warps: 4 o-blocks x 2 n-blocks)
// BM=64 o, BN=64 n, BK=32 c.  Markidis split: Wh*Xh + Wh*Xl + Wl*Xh.
__global__ void __launch_bounds__(256) conv1x1_tc_kernel(
    const float* __restrict__ X, const float* __restrict__ W,
    const float* __restrict__ bias, float* __restrict__ Cout,
    int OC, int IC)
{
    __shared__ __align__(16) __half Wh[64 * CSTR];
    __shared__ __align__(16) __half Wl[64 * CSTR];
    __shared__ __align__(16) __half Xh[64 * CSTR];
    __shared__ __align__(16) __half Xl[64 * CSTR];

    const int t    = threadIdx.x;
    const int lane = t & 31;
    const int wid  = t >> 5;
    const int o0w  = (wid & 3) * 16;
    const int n0w  = (wid >> 2) * 32;
    const int r    = lane >> 2;
    const int cc   = lane & 3;

    const int n0 = blockIdx.x * 64;
    const int o0 = blockIdx.y * 64;
    const int b  = blockIdx.z;

    const float* Xb = X + ((size_t)b * IC) * NSP + n0;

    // X transpose-load geometry
    const int nX = t & 63;
    const int cg = (t >> 6) * 4;

    float sacc[4][4];
#pragma unroll
    for (int nt = 0; nt < 4; ++nt)
#pragma unroll
        for (int e = 0; e < 4; ++e) sacc[nt][e] = 0.f;

    for (int c0 = 0; c0 < IC; c0 += 32) {
        // ---- load W tile [64 o][32 c] (c contiguous in global) ----
#pragma unroll
        for (int e = 0; e < 2; ++e) {
            int idx = t + e * 256;          // 0..511 float4 units
            int o  = idx >> 3;
            int c4 = (idx & 7) * 4;
            float4 f = *(const float4*)(W + (size_t)(o0 + o) * IC + c0 + c4);
            uint2 hi, lo;
            split4(f, hi, lo);
            *(uint2*)&Wh[o * CSTR + c4] = hi;
            *(uint2*)&Wl[o * CSTR + c4] = lo;
        }
        // ---- load X tile transposed: [64 n][32 c] ----
#pragma unroll
        for (int e = 0; e < 2; ++e) {
            int c = cg + e * 16;
            float4 f;
            f.x = Xb[(size_t)(c0 + c + 0) * NSP + nX];
            f.y = Xb[(size_t)(c0 + c + 1) * NSP + nX];
            f.z = Xb[(size_t)(c0 + c + 2) * NSP + nX];
            f.w = Xb[(size_t)(c0 + c + 3) * NSP + nX];
            uint2 hi, lo;
            split4(f, hi, lo);
            *(uint2*)&Xh[nX * CSTR + c] = hi;
            *(uint2*)&Xl[nX * CSTR + c] = lo;
        }
        __syncthreads();

#pragma unroll
        for (int ks = 0; ks < 2; ++ks) {
            const int arow = (o0w + (lane & 15)) * CSTR + ks * 16 + ((lane >> 4) << 3);
            uint32_t ah0, ah1, ah2, ah3, al0, al1, al2, al3;
            ldsm_x4(ah0, ah1, ah2, ah3, &Wh[arow]);
            ldsm_x4(al0, al1, al2, al3, &Wl[arow]);
#pragma unroll
            for (int p = 0; p < 2; ++p) {
                const int brow = (n0w + p * 16 + ((lane >> 4) << 3) + (lane & 7)) * CSTR
                               + ks * 16 + (lane & 8);
                uint32_t bh0, bh1, bh2, bh3, bl0, bl1, bl2, bl3;
                ldsm_x4(bh0, bh1, bh2, bh3, &Xh[brow]);
                ldsm_x4(bl0, bl1, bl2, bl3, &Xl[brow]);
                // hi*hi
                mma16816(sacc[2 * p],     ah0, ah1, ah2, ah3, bh0, bh1);
                mma16816(sacc[2 * p + 1], ah0, ah1, ah2, ah3, bh2, bh3);
                // hi*lo
                mma16816(sacc[2 * p],     ah0, ah1, ah2, ah3, bl0, bl1);
                mma16816(sacc[2 * p + 1], ah0, ah1, ah2, ah3, bl2, bl3);
                // lo*hi
                mma16816(sacc[2 * p],     al0, al1, al2, al3, bh0, bh1);
                mma16816(sacc[2 * p + 1], al0, al1, al2, al3, bh2, bh3);
            }
        }
        __syncthreads();
    }

    // ---- epilogue: add bias, store float2 (n, n+1 contiguous) ----
    const int o_lo = o0 + o0w + r;
    const int o_hi = o_lo + 8;
    const float blo = bias[o_lo];
    const float bhi = bias[o_hi];
    float* out_lo = Cout + ((size_t)b * OC + o_lo) * NSP + n0 + n0w;
    float* out_hi = Cout + ((size_t)b * OC + o_hi) * NSP + n0 + n0w;
#pragma unroll
    for (int nt = 0; nt < 4; ++nt) {
        int n = nt * 8 + 2 * cc;
        *(float2*)(out_lo + n) = make_float2(sacc[nt][0] + blo, sacc[nt][1] + blo);
        *(float2*)(out_hi + n) = make_float2(sacc[nt][2] + bhi, sacc[nt][3] + bhi);
    }
}

// ---------------- 3x3 depthwise conv (unchanged) ----------------
__global__ void __launch_bounds__(256) dwconv_kernel(
    const float* __restrict__ in, const float* __restrict__ wdw,
    const float* __restrict__ bias, float* __restrict__ out)
{
    const int bc = blockIdx.x;
    const int ch = bc % C3;
    const float* p = in + (size_t)bc * NSP;
    float*       q = out + (size_t)bc * NSP;

    float w9[9];
#pragma unroll
    for (int i = 0; i < 9; ++i) w9[i] = wdw[ch * 9 + i];

    const int idx = blockIdx.y * 256 + threadIdx.x;
    const int y = idx >> 6;
    const int x = idx & 63;

    float acc = bias[ch];
#pragma unroll
    for (int dy = -1; dy <= 1; ++dy) {
        int yy = y + dy;
        if (yy < 0 || yy > 63) continue;
#pragma unroll
        for (int dx = -1; dx <= 1; ++dx) {
            int xx = x + dx;
            if (xx < 0 || xx > 63) continue;
            acc += __ldg(p + yy * 64 + xx) * w9[(dy + 1) * 3 + (dx + 1)];
        }
    }
    q[idx] = acc;
}

// ---------------- L2 norm; q scaled by T*log2e ----------------
__global__ void __launch_bounds__(256) norm_kernel(float* qkv, const float* __restrict__ temp)
{
    const int bh   = blockIdx.x;
    const int b    = bh >> 2;
    const int head = bh & 3;
    const int n    = blockIdx.y * 256 + threadIdx.x;

    float* qp = qkv + ((size_t)(b * C3) + head * HD) * NSP + n;
    float* kp = qp + (size_t)CH * NSP;

    float sq = 0.f, sk = 0.f;
#pragma unroll 16
    for (int d = 0; d < HD; ++d) {
        float qv = qp[(size_t)d * NSP]; sq += qv * qv;
        float kv = kp[(size_t)d * NSP]; sk += kv * kv;
    }
    const float qs = (temp[head] * L2E) / fmaxf(sqrtf(sq), 1e-12f);
    const float ks = 1.0f / fmaxf(sqrtf(sk), 1e-12f);
#pragma unroll 16
    for (int d = 0; d < HD; ++d) {
        qp[(size_t)d * NSP] *= qs;
        kp[(size_t)d * NSP] *= ks;
    }
}

// ---------------- flash attention (unchanged from R3) ----------------
__global__ void __launch_bounds__(256) attn_kernel(
    const float* __restrict__ qkv, const float* __restrict__ temp, float* __restrict__ out)
{
    __shared__ __align__(16) __half Qs[64 * QKSTR];
    __shared__ __align__(16) __half Ks[2][64 * QKSTR];
    __shared__ __align__(16) __half Vs[2][HD * VSTR];
    __shared__ float lred[128];

    const int t    = threadIdx.x;
    const int lane = t & 31;
    const int wid  = t >> 5;
    const int wi   = wid & 3;
    const int wj   = wid >> 2;
    const int i0   = wi * 16;
    const int r    = lane >> 2;
    const int cc   = lane & 3;

    const int bh   = blockIdx.y;
    const int b    = bh >> 2;
    const int head = bh & 3;
    const int n0   = blockIdx.x * 64;

    const float* qbase = qkv + ((size_t)(b * C3) + head * HD) * NSP;
    const float* kbase = qbase + (size_t)CH * NSP;
    const float* vbase = kbase + (size_t)CH * NSP;
    const float  cbias = fabsf(temp[head]) * L2E;

    const int jK = t & 63;
    const int dg = (t >> 6) * 4;

#pragma unroll
    for (int e = 0; e < 3; ++e) {
        int d0 = dg + e * 16;
        float f0 = qbase[(size_t)(d0 + 0) * NSP + n0 + jK];
        float f1 = qbase[(size_t)(d0 + 1) * NSP + n0 + jK];
        float f2 = qbase[(size_t)(d0 + 2) * NSP + n0 + jK];
        float f3 = qbase[(size_t)(d0 + 3) * NSP + n0 + jK];
        *(uint2*)&Qs[jK * QKSTR + d0] = make_uint2(cvt2(f1, f0), cvt2(f3, f2));
    }
#pragma unroll
    for (int e = 0; e < 3; ++e) {
        int d0 = dg + e * 16;
        float f0 = kbase[(size_t)(d0 + 0) * NSP + jK];
        float f1 = kbase[(size_t)(d0 + 1) * NSP + jK];
        float f2 = kbase[(size_t)(d0 + 2) * NSP + jK];
        float f3 = kbase[(size_t)(d0 + 3) * NSP + jK];
        *(uint2*)&Ks[0][jK * QKSTR + d0] = make_uint2(cvt2(f1, f0), cvt2(f3, f2));
    }
#pragma unroll
    for (int e = 0; e < 3; ++e) {
        int lin = t + e * 256;
        int dv = lin >> 4, j4 = (lin & 15) * 4;
        float4 v = *(const float4*)(vbase + (size_t)dv * NSP + j4);
        *(uint2*)&Vs[0][dv * VSTR + j4] = make_uint2(cvt2(v.y, v.x), cvt2(v.w, v.z));
    }

    float oacc[6][4];
#pragma unroll
    for (int nt = 0; nt < 6; ++nt)
#pragma unroll
        for (int e = 0; e < 4; ++e) oacc[nt][e] = 0.f;
    float l_lo = 0.f, l_hi = 0.f;

    __syncthreads();

    for (int it = 0; it < NSP / 64; ++it) {
        const int cur = it & 1;
        const __half* Kc = Ks[cur];
        const __half* Vc = Vs[cur];
        const bool has_next = (it < NSP / 64 - 1);
        const int m0n = (it + 1) * 64;

        float kf[3][4];
        float4 vf[3];
        if (has_next) {
#pragma unroll
            for (int e = 0; e < 3; ++e) {
                int d0 = dg + e * 16;
                kf[e][0] = kbase[(size_t)(d0 + 0) * NSP + m0n + jK];
                kf[e][1] = kbase[(size_t)(d0 + 1) * NSP + m0n + jK];
                kf[e][2] = kbase[(size_t)(d0 + 2) * NSP + m0n + jK];
                kf[e][3] = kbase[(size_t)(d0 + 3) * NSP + m0n + jK];
            }
#pragma unroll
            for (int e = 0; e < 3; ++e) {
                int lin = t + e * 256;
                int dv = lin >> 4, j4 = (lin & 15) * 4;
                vf[e] = *(const float4*)(vbase + (size_t)dv * NSP + m0n + j4);
            }
        }

        float sacc[4][4];
#pragma unroll
        for (int nt = 0; nt < 4; ++nt)
#pragma unroll
            for (int e = 0; e < 4; ++e) sacc[nt][e] = 0.f;

#pragma unroll
        for (int ks = 0; ks < 3; ++ks) {
            uint32_t a0, a1, a2, a3;
            ldsm_x4(a0, a1, a2, a3,
                    &Qs[(i0 + (lane & 15)) * QKSTR + ks * 16 + ((lane >> 4) << 3)]);
#pragma unroll
            for (int p = 0; p < 2; ++p) {
                uint32_t b0, b1, b2, b3;
                int row = wj * 32 + p * 16 + ((lane >> 4) << 3) + (lane & 7);
                int col = ks * 16 + (lane & 8);
                ldsm_x4(b0, b1, b2, b3, &Kc[row * QKSTR + col]);
                mma16816(sacc[2 * p],     a0, a1, a2, a3, b0, b1);
                mma16816(sacc[2 * p + 1], a0, a1, a2, a3, b2, b3);
            }
        }

        uint32_t plo[4], phi[4];
        uint32_t sum_lo = 0, sum_hi = 0;
#pragma unroll
        for (int nt = 0; nt < 4; ++nt) {
            plo[nt] = ex2h2(cvt2(sacc[nt][1] - cbias, sacc[nt][0] - cbias));
            phi[nt] = ex2h2(cvt2(sacc[nt][3] - cbias, sacc[nt][2] - cbias));
            sum_lo = hadd2(sum_lo, plo[nt]);
            sum_hi = hadd2(sum_hi, phi[nt]);
        }
        {
            float2 f0 = h22f2(sum_lo); l_lo += f0.x + f0.y;
            float2 f1 = h22f2(sum_hi); l_hi += f1.x + f1.y;
        }

#pragma unroll
        for (int nt = 0; nt < 6; ++nt) {
            uint32_t b0, b1, b2, b3;
            ldsm_x4(b0, b1, b2, b3,
                    &Vc[(nt * 8 + (lane & 7)) * VSTR + wj * 32 + ((lane >> 3) & 3) * 8]);
            mma16816(oacc[nt], plo[0], phi[0], plo[1], phi[1], b0, b1);
            mma16816(oacc[nt], plo[2], phi[2], plo[3], phi[3], b2, b3);
        }

        if (has_next) {
            const int nb = cur ^ 1;
#pragma unroll
            for (int e = 0; e < 3; ++e) {
                int d0 = dg + e * 16;
                *(uint2*)&Ks[nb][jK * QKSTR + d0] =
                    make_uint2(cvt2(kf[e][1], kf[e][0]), cvt2(kf[e][3], kf[e][2]));
            }
#pragma unroll
            for (int e = 0; e < 3; ++e) {
                int lin = t + e * 256;
                int dv = lin >> 4, j4 = (lin & 15) * 4;
                *(uint2*)&Vs[nb][dv * VSTR + j4] =
                    make_uint2(cvt2(vf[e].y, vf[e].x), cvt2(vf[e].w, vf[e].z));
            }
        }
        __syncthreads();
    }

    l_lo += __shfl_xor_sync(0xffffffffu, l_lo, 1);
    l_lo += __shfl_xor_sync(0xffffffffu, l_lo, 2);
    l_hi += __shfl_xor_sync(0xffffffffu, l_hi, 1);
    l_hi += __shfl_xor_sync(0xffffffffu, l_hi, 2);
    if (cc == 0) {
        lred[wj * 64 + i0 + r]     = l_lo;
        lred[wj * 64 + i0 + r + 8] = l_hi;
    }
    float* Ored = (float*)&Ks[0][0];
    if (wj == 1) {
#pragma unroll
        for (int nt = 0; nt < 6; ++nt) {
            int d = nt * 8 + 2 * cc;
            Ored[(i0 + r) * 48 + d]         = oacc[nt][0];
            Ored[(i0 + r) * 48 + d + 1]     = oacc[nt][1];
            Ored[(i0 + r + 8) * 48 + d]     = oacc[nt][2];
            Ored[(i0 + r + 8) * 48 + d + 1] = oacc[nt][3];
        }
    }
    __syncthreads();
    if (wj == 0) {
        float linv_lo = 1.f / (lred[i0 + r]     + lred[64 + i0 + r]);
        float linv_hi = 1.f / (lred[i0 + r + 8] + lred[64 + i0 + r + 8]);
        float* ob = out + ((size_t)(b * CH) + head * HD) * NSP + n0;
#pragma unroll
        for (int nt = 0; nt < 6; ++nt) {
            int d = nt * 8 + 2 * cc;
            ob[(size_t)d * NSP + i0 + r]           = (oacc[nt][0] + Ored[(i0 + r) * 48 + d])         * linv_lo;
            ob[(size_t)(d + 1) * NSP + i0 + r]     = (oacc[nt][1] + Ored[(i0 + r) * 48 + d + 1])     * linv_lo;
            ob[(size_t)d * NSP + i0 + r + 8]       = (oacc[nt][2] + Ored[(i0 + r + 8) * 48 + d])     * linv_hi;
            ob[(size_t)(d + 1) * NSP + i0 + r + 8] = (oacc[nt][3] + Ored[(i0 + r + 8) * 48 + d + 1]) * linv_hi;
        }
    }
}

// ---------------- launcher ----------------
extern "C" void kernel_launch(void* const* d_in, const int* in_sizes, int n_in,
                              void* d_out, int out_size)
{
    const float* x      = (const float*)d_in[0];
    const float* w_qkv  = (const float*)d_in[1];
    const float* b_qkv  = (const float*)d_in[2];
    const float* w_dw   = (const float*)d_in[3];
    const float* b_dw   = (const float*)d_in[4];
    const float* w_proj = (const float*)d_in[5];
    const float* b_proj = (const float*)d_in[6];
    const float* temp   = (const float*)d_in[7];
    float* out = (float*)d_out;

    float* qkv1; cudaGetSymbolAddress((void**)&qkv1, g_qkv);
    float* qkv2; cudaGetSymbolAddress((void**)&qkv2, g_qkv2);
    float* att;  cudaGetSymbolAddress((void**)&att,  g_att);

    conv1x1_tc_kernel<<<dim3(NSP / 64, C3 / 64, B2), 256>>>(x, w_qkv, b_qkv, qkv1, C3, CH);
    dwconv_kernel<<<dim3(B2 * C3, NSP / 256), 256>>>(qkv1, w_dw, b_dw, qkv2);
    norm_kernel<<<dim3(B2 * HEADS, NSP / 256), 256>>>(qkv2, temp);
    attn_kernel<<<dim3(NSP / 64, B2 * HEADS), 256>>>(qkv2, temp, att);
    conv1x1_tc_kernel<<<dim3(NSP / 64, CH / 64, B2), 256>>>(att, w_proj, b_proj, out, CH, CH);
}

// round 5
// speedup vs baseline: 6.4755x; 1.2277x over previous
#include <cuda_runtime.h>
#include <cuda_fp16.h>
#include <cstdint>

#define B2     2
#define CH     192
#define C3     (3*CH)
#define HEADS  4
#define HD     48
#define NSP    4096
#define L2E    1.44269504f

#define QKSTR 56   // half stride: 7 16B-chunks (odd mod 8) -> ldmatrix conflict-free
#define VSTR  72   // 9 chunks
#define CSTR  40   // conv tiles: 5 chunks

// ---------------- scratch ----------------
__device__ float  g_qkv [B2 * C3 * NSP];
__device__ float  g_qkv2[B2 * C3 * NSP];          // q,k float (pre-norm)
__device__ float  g_att [B2 * CH * NSP];
__device__ __half g_qh  [B2 * HEADS * NSP * HD];  // normalized q, [bh][n][d]
__device__ __half g_kh  [B2 * HEADS * NSP * HD];  // normalized k, [bh][n][d]
__device__ __half g_vh  [B2 * CH * NSP];          // v fp16, [b][c][n]

// ---------------- asm helpers ----------------
__device__ __forceinline__ uint32_t sptr(const void* p) {
    return (uint32_t)__cvta_generic_to_shared(p);
}
__device__ __forceinline__ void ldsm_x4(uint32_t& r0, uint32_t& r1, uint32_t& r2, uint32_t& r3,
                                        const __half* p) {
    asm volatile("ldmatrix.sync.aligned.m8n8.x4.shared.b16 {%0,%1,%2,%3}, [%4];"
                 : "=r"(r0), "=r"(r1), "=r"(r2), "=r"(r3) : "r"(sptr(p)));
}
__device__ __forceinline__ void mma16816(float c[4],
                                         uint32_t a0, uint32_t a1, uint32_t a2, uint32_t a3,
                                         uint32_t b0, uint32_t b1) {
    asm volatile(
        "mma.sync.aligned.m16n8k16.row.col.f32.f16.f16.f32 "
        "{%0,%1,%2,%3}, {%4,%5,%6,%7}, {%8,%9}, {%0,%1,%2,%3};"
        : "+f"(c[0]), "+f"(c[1]), "+f"(c[2]), "+f"(c[3])
        : "r"(a0), "r"(a1), "r"(a2), "r"(a3), "r"(b0), "r"(b1));
}
__device__ __forceinline__ uint32_t cvt2(float hi, float lo) {
    uint32_t r;
    asm("cvt.rn.f16x2.f32 %0, %1, %2;" : "=r"(r) : "f"(hi), "f"(lo));
    return r;
}
__device__ __forceinline__ uint32_t ex2h2(uint32_t x) {
    uint32_t r;
    asm("ex2.approx.f16x2 %0, %1;" : "=r"(r) : "r"(x));
    return r;
}
__device__ __forceinline__ uint32_t hadd2(uint32_t a, uint32_t b) {
    uint32_t r;
    asm("add.rn.f16x2 %0, %1, %2;" : "=r"(r) : "r"(a), "r"(b));
    return r;
}
__device__ __forceinline__ float2 h22f2(uint32_t u) {
    __half2 h = *reinterpret_cast<__half2*>(&u);
    return __half22float2(h);
}
__device__ __forceinline__ void split4(float4 f, uint2& hi, uint2& lo) {
    hi = make_uint2(cvt2(f.y, f.x), cvt2(f.w, f.z));
    float2 g0 = h22f2(hi.x), g1 = h22f2(hi.y);
    lo = make_uint2(cvt2(f.y - g0.y, f.x - g0.x), cvt2(f.w - g1.y, f.z - g1.x));
}
__device__ __forceinline__ void cp16(const __half* smem_dst, const __half* gsrc) {
    asm volatile("cp.async.cg.shared.global [%0], [%1], 16;"
                 :: "r"(sptr(smem_dst)), "l"(gsrc));
}
__device__ __forceinline__ void cp_commit() { asm volatile("cp.async.commit_group;"); }
__device__ __forceinline__ void cp_wait0()  { asm volatile("cp.async.wait_group 0;"); }

// ---------------- 1x1 conv as split-fp16 tensor GEMM (unchanged from R4) ----------------
__global__ void __launch_bounds__(256) conv1x1_tc_kernel(
    const float* __restrict__ X, const float* __restrict__ W,
    const float* __restrict__ bias, float* __restrict__ Cout,
    int OC, int IC)
{
    __shared__ __align__(16) __half Wh[64 * CSTR];
    __shared__ __align__(16) __half Wl[64 * CSTR];
    __shared__ __align__(16) __half Xh[64 * CSTR];
    __shared__ __align__(16) __half Xl[64 * CSTR];

    const int t    = threadIdx.x;
    const int lane = t & 31;
    const int wid  = t >> 5;
    const int o0w  = (wid & 3) * 16;
    const int n0w  = (wid >> 2) * 32;
    const int r    = lane >> 2;
    const int cc   = lane & 3;

    const int n0 = blockIdx.x * 64;
    const int o0 = blockIdx.y * 64;
    const int b  = blockIdx.z;

    const float* Xb = X + ((size_t)b * IC) * NSP + n0;

    const int nX = t & 63;
    const int cg = (t >> 6) * 4;

    float sacc[4][4];
#pragma unroll
    for (int nt = 0; nt < 4; ++nt)
#pragma unroll
        for (int e = 0; e < 4; ++e) sacc[nt][e] = 0.f;

    for (int c0 = 0; c0 < IC; c0 += 32) {
#pragma unroll
        for (int e = 0; e < 2; ++e) {
            int idx = t + e * 256;
            int o  = idx >> 3;
            int c4 = (idx & 7) * 4;
            float4 f = *(const float4*)(W + (size_t)(o0 + o) * IC + c0 + c4);
            uint2 hi, lo;
            split4(f, hi, lo);
            *(uint2*)&Wh[o * CSTR + c4] = hi;
            *(uint2*)&Wl[o * CSTR + c4] = lo;
        }
#pragma unroll
        for (int e = 0; e < 2; ++e) {
            int c = cg + e * 16;
            float4 f;
            f.x = Xb[(size_t)(c0 + c + 0) * NSP + nX];
            f.y = Xb[(size_t)(c0 + c + 1) * NSP + nX];
            f.z = Xb[(size_t)(c0 + c + 2) * NSP + nX];
            f.w = Xb[(size_t)(c0 + c + 3) * NSP + nX];
            uint2 hi, lo;
            split4(f, hi, lo);
            *(uint2*)&Xh[nX * CSTR + c] = hi;
            *(uint2*)&Xl[nX * CSTR + c] = lo;
        }
        __syncthreads();

#pragma unroll
        for (int ks = 0; ks < 2; ++ks) {
            const int arow = (o0w + (lane & 15)) * CSTR + ks * 16 + ((lane >> 4) << 3);
            uint32_t ah0, ah1, ah2, ah3, al0, al1, al2, al3;
            ldsm_x4(ah0, ah1, ah2, ah3, &Wh[arow]);
            ldsm_x4(al0, al1, al2, al3, &Wl[arow]);
#pragma unroll
            for (int p = 0; p < 2; ++p) {
                const int brow = (n0w + p * 16 + ((lane >> 4) << 3) + (lane & 7)) * CSTR
                               + ks * 16 + (lane & 8);
                uint32_t bh0, bh1, bh2, bh3, bl0, bl1, bl2, bl3;
                ldsm_x4(bh0, bh1, bh2, bh3, &Xh[brow]);
                ldsm_x4(bl0, bl1, bl2, bl3, &Xl[brow]);
                mma16816(sacc[2 * p],     ah0, ah1, ah2, ah3, bh0, bh1);
                mma16816(sacc[2 * p + 1], ah0, ah1, ah2, ah3, bh2, bh3);
                mma16816(sacc[2 * p],     ah0, ah1, ah2, ah3, bl0, bl1);
                mma16816(sacc[2 * p + 1], ah0, ah1, ah2, ah3, bl2, bl3);
                mma16816(sacc[2 * p],     al0, al1, al2, al3, bh0, bh1);
                mma16816(sacc[2 * p + 1], al0, al1, al2, al3, bh2, bh3);
            }
        }
        __syncthreads();
    }

    const int o_lo = o0 + o0w + r;
    const int o_hi = o_lo + 8;
    const float blo = bias[o_lo];
    const float bhi = bias[o_hi];
    float* out_lo = Cout + ((size_t)b * OC + o_lo) * NSP + n0 + n0w;
    float* out_hi = Cout + ((size_t)b * OC + o_hi) * NSP + n0 + n0w;
#pragma unroll
    for (int nt = 0; nt < 4; ++nt) {
        int n = nt * 8 + 2 * cc;
        *(float2*)(out_lo + n) = make_float2(sacc[nt][0] + blo, sacc[nt][1] + blo);
        *(float2*)(out_hi + n) = make_float2(sacc[nt][2] + bhi, sacc[nt][3] + bhi);
    }
}

// ---------------- 3x3 depthwise conv; v channels emitted as fp16 ----------------
__global__ void __launch_bounds__(256) dwconv_kernel(
    const float* __restrict__ in, const float* __restrict__ wdw,
    const float* __restrict__ bias, float* __restrict__ out, __half* __restrict__ vh)
{
    const int bc = blockIdx.x;
    const int ch = bc % C3;
    const int b  = bc / C3;
    const float* p = in + (size_t)bc * NSP;

    float w9[9];
#pragma unroll
    for (int i = 0; i < 9; ++i) w9[i] = wdw[ch * 9 + i];

    const int idx = blockIdx.y * 256 + threadIdx.x;
    const int y = idx >> 6;
    const int x = idx & 63;

    float acc = bias[ch];
#pragma unroll
    for (int dy = -1; dy <= 1; ++dy) {
        int yy = y + dy;
        if (yy < 0 || yy > 63) continue;
#pragma unroll
        for (int dx = -1; dx <= 1; ++dx) {
            int xx = x + dx;
            if (xx < 0 || xx > 63) continue;
            acc += __ldg(p + yy * 64 + xx) * w9[(dy + 1) * 3 + (dx + 1)];
        }
    }
    if (ch < 2 * CH) {
        out[(size_t)bc * NSP + idx] = acc;
    } else {
        vh[((size_t)b * CH + (ch - 2 * CH)) * NSP + idx] = __float2half(acc);
    }
}

// ---------------- L2 norm -> fp16 [bh][n][48] (q scaled by T*log2e) ----------------
__global__ void __launch_bounds__(256) norm_kernel(
    const float* __restrict__ qkv, __half* __restrict__ qh, __half* __restrict__ kh,
    const float* __restrict__ temp)
{
    const int bh   = blockIdx.x;
    const int b    = bh >> 2;
    const int head = bh & 3;
    const int n    = blockIdx.y * 256 + threadIdx.x;

    const float* qp = qkv + ((size_t)(b * C3) + head * HD) * NSP + n;
    const float* kp = qp + (size_t)CH * NSP;

    float sq = 0.f, sk = 0.f;
#pragma unroll 16
    for (int d = 0; d < HD; ++d) {
        float qv = qp[(size_t)d * NSP]; sq += qv * qv;
        float kv = kp[(size_t)d * NSP]; sk += kv * kv;
    }
    const float qs = (temp[head] * L2E) / fmaxf(sqrtf(sq), 1e-12f);
    const float ks = 1.0f / fmaxf(sqrtf(sk), 1e-12f);

    __half* qo = qh + ((size_t)bh * NSP + n) * HD;
    __half* ko = kh + ((size_t)bh * NSP + n) * HD;
#pragma unroll
    for (int g = 0; g < 6; ++g) {
        float q0 = qp[(size_t)(g * 8 + 0) * NSP] * qs, q1 = qp[(size_t)(g * 8 + 1) * NSP] * qs;
        float q2 = qp[(size_t)(g * 8 + 2) * NSP] * qs, q3 = qp[(size_t)(g * 8 + 3) * NSP] * qs;
        float q4 = qp[(size_t)(g * 8 + 4) * NSP] * qs, q5 = qp[(size_t)(g * 8 + 5) * NSP] * qs;
        float q6 = qp[(size_t)(g * 8 + 6) * NSP] * qs, q7 = qp[(size_t)(g * 8 + 7) * NSP] * qs;
        *(uint4*)(qo + g * 8) = make_uint4(cvt2(q1, q0), cvt2(q3, q2), cvt2(q5, q4), cvt2(q7, q6));
        float k0 = kp[(size_t)(g * 8 + 0) * NSP] * ks, k1 = kp[(size_t)(g * 8 + 1) * NSP] * ks;
        float k2 = kp[(size_t)(g * 8 + 2) * NSP] * ks, k3 = kp[(size_t)(g * 8 + 3) * NSP] * ks;
        float k4 = kp[(size_t)(g * 8 + 4) * NSP] * ks, k5 = kp[(size_t)(g * 8 + 5) * NSP] * ks;
        float k6 = kp[(size_t)(g * 8 + 6) * NSP] * ks, k7 = kp[(size_t)(g * 8 + 7) * NSP] * ks;
        *(uint4*)(ko + g * 8) = make_uint4(cvt2(k1, k0), cvt2(k3, k2), cvt2(k5, k4), cvt2(k7, k6));
    }
}

// ---------------- flash attention: cp.async streamed fp16 tiles ----------------
// grid: (64, 8), block 256 (8 warps: wi in [0,4) x wj in [0,2))
__global__ void __launch_bounds__(256) attn_kernel(
    const __half* __restrict__ qh, const __half* __restrict__ kh,
    const __half* __restrict__ vh, const float* __restrict__ temp,
    float* __restrict__ out)
{
    __shared__ __align__(16) __half Qs[64 * QKSTR];
    __shared__ __align__(16) __half Ks[2][64 * QKSTR];
    __shared__ __align__(16) __half Vs[2][HD * VSTR];
    __shared__ float lred[128];

    const int t    = threadIdx.x;
    const int lane = t & 31;
    const int wid  = t >> 5;
    const int wi   = wid & 3;
    const int wj   = wid >> 2;
    const int i0   = wi * 16;
    const int r    = lane >> 2;
    const int cc   = lane & 3;

    const int bh   = blockIdx.y;
    const int b    = bh >> 2;
    const int head = bh & 3;
    const int n0   = blockIdx.x * 64;

    const __half* qb = qh + (size_t)bh * NSP * HD;
    const __half* kb = kh + (size_t)bh * NSP * HD;
    const __half* vb = vh + ((size_t)b * CH + head * HD) * NSP;
    const float   cbias = fabsf(temp[head]) * L2E;

    // ---- prologue: cp.async Q tile + K0,V0 ----
    // Q/K tiles: 64 rows x 48 halves (6 chunks/row) = 384 chunks
    // V tiles:   48 rows x 64 halves (8 chunks/row) = 384 chunks
    {
        int ch = t, row = ch / 6, c = ch % 6;
        cp16(&Qs[row * QKSTR + c * 8], qb + ((size_t)(n0 + row)) * HD + c * 8);
        cp16(&Ks[0][row * QKSTR + c * 8], kb + ((size_t)row) * HD + c * 8);
    }
    if (t < 128) {
        int ch = t + 256, row = ch / 6, c = ch % 6;
        cp16(&Qs[row * QKSTR + c * 8], qb + ((size_t)(n0 + row)) * HD + c * 8);
        cp16(&Ks[0][row * QKSTR + c * 8], kb + ((size_t)row) * HD + c * 8);
    }
    {
        int ch = t, row = ch >> 3, c = ch & 7;
        cp16(&Vs[0][row * VSTR + c * 8], vb + (size_t)row * NSP + c * 8);
    }
    if (t < 128) {
        int ch = t + 256, row = ch >> 3, c = ch & 7;
        cp16(&Vs[0][row * VSTR + c * 8], vb + (size_t)row * NSP + c * 8);
    }
    cp_commit();

    float oacc[6][4];
#pragma unroll
    for (int nt = 0; nt < 6; ++nt)
#pragma unroll
        for (int e = 0; e < 4; ++e) oacc[nt][e] = 0.f;
    float l_lo = 0.f, l_hi = 0.f;

    // precomputed per-thread load coords
    const int krow0 = t / 6,          kc0 = (t % 6) * 8;
    const int krow1 = (t + 256) / 6,  kc1 = ((t + 256) % 6) * 8;
    const int vrow0 = t >> 3,         vc0 = (t & 7) * 8;
    const int vrow1 = (t + 256) >> 3, vc1 = ((t + 256) & 7) * 8;

    for (int it = 0; it < NSP / 64; ++it) {
        const int cur = it & 1;
        const __half* Kc = Ks[cur];
        const __half* Vc = Vs[cur];
        const bool has_next = (it < NSP / 64 - 1);

        cp_wait0();
        __syncthreads();

        if (has_next) {
            const int nb = cur ^ 1;
            const int m0n = (it + 1) * 64;
            cp16(&Ks[nb][krow0 * QKSTR + kc0], kb + ((size_t)(m0n + krow0)) * HD + kc0);
            if (t < 128)
                cp16(&Ks[nb][krow1 * QKSTR + kc1], kb + ((size_t)(m0n + krow1)) * HD + kc1);
            cp16(&Vs[nb][vrow0 * VSTR + vc0], vb + (size_t)vrow0 * NSP + m0n + vc0);
            if (t < 128)
                cp16(&Vs[nb][vrow1 * VSTR + vc1], vb + (size_t)vrow1 * NSP + m0n + vc1);
            cp_commit();
        }

        // ---- S = Q K^T (warp: 16i x 32j) ----
        float sacc[4][4];
#pragma unroll
        for (int nt = 0; nt < 4; ++nt)
#pragma unroll
            for (int e = 0; e < 4; ++e) sacc[nt][e] = 0.f;

#pragma unroll
        for (int ks = 0; ks < 3; ++ks) {
            uint32_t a0, a1, a2, a3;
            ldsm_x4(a0, a1, a2, a3,
                    &Qs[(i0 + (lane & 15)) * QKSTR + ks * 16 + ((lane >> 4) << 3)]);
#pragma unroll
            for (int p = 0; p < 2; ++p) {
                uint32_t b0, b1, b2, b3;
                int row = wj * 32 + p * 16 + ((lane >> 4) << 3) + (lane & 7);
                int col = ks * 16 + (lane & 8);
                ldsm_x4(b0, b1, b2, b3, &Kc[row * QKSTR + col]);
                mma16816(sacc[2 * p],     a0, a1, a2, a3, b0, b1);
                mma16816(sacc[2 * p + 1], a0, a1, a2, a3, b2, b3);
            }
        }

        // ---- softmax in registers: P = exp2(S - c) ----
        uint32_t plo[4], phi[4];
        uint32_t sum_lo = 0, sum_hi = 0;
#pragma unroll
        for (int nt = 0; nt < 4; ++nt) {
            plo[nt] = ex2h2(cvt2(sacc[nt][1] - cbias, sacc[nt][0] - cbias));
            phi[nt] = ex2h2(cvt2(sacc[nt][3] - cbias, sacc[nt][2] - cbias));
            sum_lo = hadd2(sum_lo, plo[nt]);
            sum_hi = hadd2(sum_hi, phi[nt]);
        }
        {
            float2 f0 = h22f2(sum_lo); l_lo += f0.x + f0.y;
            float2 f1 = h22f2(sum_hi); l_hi += f1.x + f1.y;
        }

        // ---- O += P V^T (warp: 16i x 48d, partial over its 32 j) ----
#pragma unroll
        for (int nt = 0; nt < 6; ++nt) {
            uint32_t b0, b1, b2, b3;
            ldsm_x4(b0, b1, b2, b3,
                    &Vc[(nt * 8 + (lane & 7)) * VSTR + wj * 32 + ((lane >> 3) & 3) * 8]);
            mma16816(oacc[nt], plo[0], phi[0], plo[1], phi[1], b0, b1);
            mma16816(oacc[nt], plo[2], phi[2], plo[3], phi[3], b2, b3);
        }
    }

    // ---- epilogue ----
    l_lo += __shfl_xor_sync(0xffffffffu, l_lo, 1);
    l_lo += __shfl_xor_sync(0xffffffffu, l_lo, 2);
    l_hi += __shfl_xor_sync(0xffffffffu, l_hi, 1);
    l_hi += __shfl_xor_sync(0xffffffffu, l_hi, 2);
    if (cc == 0) {
        lred[wj * 64 + i0 + r]     = l_lo;
        lred[wj * 64 + i0 + r + 8] = l_hi;
    }
    float* Ored = (float*)&Ks[0][0];   // safe: last tile used Ks[1]/Vs[1]? (it=63 -> cur=1) yes
    if (wj == 1) {
#pragma unroll
        for (int nt = 0; nt < 6; ++nt) {
            int d = nt * 8 + 2 * cc;
            Ored[(i0 + r) * 48 + d]         = oacc[nt][0];
            Ored[(i0 + r) * 48 + d + 1]     = oacc[nt][1];
            Ored[(i0 + r + 8) * 48 + d]     = oacc[nt][2];
            Ored[(i0 + r + 8) * 48 + d + 1] = oacc[nt][3];
        }
    }
    __syncthreads();
    if (wj == 0) {
        float linv_lo = 1.f / (lred[i0 + r]     + lred[64 + i0 + r]);
        float linv_hi = 1.f / (lred[i0 + r + 8] + lred[64 + i0 + r + 8]);
        float* ob = out + ((size_t)(b * CH) + head * HD) * NSP + n0;
#pragma unroll
        for (int nt = 0; nt < 6; ++nt) {
            int d = nt * 8 + 2 * cc;
            ob[(size_t)d * NSP + i0 + r]           = (oacc[nt][0] + Ored[(i0 + r) * 48 + d])         * linv_lo;
            ob[(size_t)(d + 1) * NSP + i0 + r]     = (oacc[nt][1] + Ored[(i0 + r) * 48 + d + 1])     * linv_lo;
            ob[(size_t)d * NSP + i0 + r + 8]       = (oacc[nt][2] + Ored[(i0 + r + 8) * 48 + d])     * linv_hi;
            ob[(size_t)(d + 1) * NSP + i0 + r + 8] = (oacc[nt][3] + Ored[(i0 + r + 8) * 48 + d + 1]) * linv_hi;
        }
    }
}

// ---------------- launcher ----------------
extern "C" void kernel_launch(void* const* d_in, const int* in_sizes, int n_in,
                              void* d_out, int out_size)
{
    const float* x      = (const float*)d_in[0];
    const float* w_qkv  = (const float*)d_in[1];
    const float* b_qkv  = (const float*)d_in[2];
    const float* w_dw   = (const float*)d_in[3];
    const float* b_dw   = (const float*)d_in[4];
    const float* w_proj = (const float*)d_in[5];
    const float* b_proj = (const float*)d_in[6];
    const float* temp   = (const float*)d_in[7];
    float* out = (float*)d_out;

    float*  qkv1; cudaGetSymbolAddress((void**)&qkv1, g_qkv);
    float*  qkv2; cudaGetSymbolAddress((void**)&qkv2, g_qkv2);
    float*  att;  cudaGetSymbolAddress((void**)&att,  g_att);
    __half* qhp;  cudaGetSymbolAddress((void**)&qhp,  g_qh);
    __half* khp;  cudaGetSymbolAddress((void**)&khp,  g_kh);
    __half* vhp;  cudaGetSymbolAddress((void**)&vhp,  g_vh);

    conv1x1_tc_kernel<<<dim3(NSP / 64, C3 / 64, B2), 256>>>(x, w_qkv, b_qkv, qkv1, C3, CH);
    dwconv_kernel<<<dim3(B2 * C3, NSP / 256), 256>>>(qkv1, w_dw, b_dw, qkv2, vhp);
    norm_kernel<<<dim3(B2 * HEADS, NSP / 256), 256>>>(qkv2, qhp, khp, temp);
    attn_kernel<<<dim3(NSP / 64, B2 * HEADS), 256>>>(qhp, khp, vhp, temp, att);
    conv1x1_tc_kernel<<<dim3(NSP / 64, CH / 64, B2), 256>>>(att, w_proj, b_proj, out, CH, CH);
}

// round 6
// speedup vs baseline: 7.0736x; 1.0924x over previous
#include <cuda_runtime.h>
#include <cuda_fp16.h>
#include <cstdint>

#define B2     2
#define CH     192
#define C3     (3*CH)
#define HEADS  4
#define HD     48
#define NSP    4096
#define L2E    1.44269504f

#define QKSTR 56   // half stride: 7 16B-chunks (odd mod 8) -> ldmatrix conflict-free
#define VSTR  72   // 9 chunks
#define CSTR  40   // conv tiles: 5 chunks

// ---------------- scratch ----------------
__device__ float  g_qkv [B2 * C3 * NSP];
__device__ float  g_qkv2[B2 * C3 * NSP];
__device__ float  g_att [B2 * CH * NSP];
__device__ __half g_qh  [B2 * HEADS * NSP * HD];  // normalized q, [bh][n][d]
__device__ __half g_kh  [B2 * HEADS * NSP * HD];  // normalized k, [bh][n][d]
__device__ __half g_vh  [B2 * CH * NSP];          // v fp16, [b][c][n]

// ---------------- asm helpers ----------------
__device__ __forceinline__ uint32_t sptr(const void* p) {
    return (uint32_t)__cvta_generic_to_shared(p);
}
__device__ __forceinline__ void ldsm_x4(uint32_t& r0, uint32_t& r1, uint32_t& r2, uint32_t& r3,
                                        const __half* p) {
    asm volatile("ldmatrix.sync.aligned.m8n8.x4.shared.b16 {%0,%1,%2,%3}, [%4];"
                 : "=r"(r0), "=r"(r1), "=r"(r2), "=r"(r3) : "r"(sptr(p)));
}
__device__ __forceinline__ void mma16816(float c[4],
                                         uint32_t a0, uint32_t a1, uint32_t a2, uint32_t a3,
                                         uint32_t b0, uint32_t b1) {
    asm volatile(
        "mma.sync.aligned.m16n8k16.row.col.f32.f16.f16.f32 "
        "{%0,%1,%2,%3}, {%4,%5,%6,%7}, {%8,%9}, {%0,%1,%2,%3};"
        : "+f"(c[0]), "+f"(c[1]), "+f"(c[2]), "+f"(c[3])
        : "r"(a0), "r"(a1), "r"(a2), "r"(a3), "r"(b0), "r"(b1));
}
__device__ __forceinline__ uint32_t cvt2(float hi, float lo) {
    uint32_t r;
    asm("cvt.rn.f16x2.f32 %0, %1, %2;" : "=r"(r) : "f"(hi), "f"(lo));
    return r;
}
__device__ __forceinline__ uint32_t ex2h2(uint32_t x) {
    uint32_t r;
    asm("ex2.approx.f16x2 %0, %1;" : "=r"(r) : "r"(x));
    return r;
}
__device__ __forceinline__ uint32_t hadd2(uint32_t a, uint32_t b) {
    uint32_t r;
    asm("add.rn.f16x2 %0, %1, %2;" : "=r"(r) : "r"(a), "r"(b));
    return r;
}
__device__ __forceinline__ float2 h22f2(uint32_t u) {
    __half2 h = *reinterpret_cast<__half2*>(&u);
    return __half22float2(h);
}
__device__ __forceinline__ void split4(float4 f, uint2& hi, uint2& lo) {
    hi = make_uint2(cvt2(f.y, f.x), cvt2(f.w, f.z));
    float2 g0 = h22f2(hi.x), g1 = h22f2(hi.y);
    lo = make_uint2(cvt2(f.y - g0.y, f.x - g0.x), cvt2(f.w - g1.y, f.z - g1.x));
}
__device__ __forceinline__ void cp16(const __half* smem_dst, const __half* gsrc) {
    asm volatile("cp.async.cg.shared.global [%0], [%1], 16;"
                 :: "r"(sptr(smem_dst)), "l"(gsrc));
}
__device__ __forceinline__ void cp_commit() { asm volatile("cp.async.commit_group;"); }
__device__ __forceinline__ void cp_wait0()  { asm volatile("cp.async.wait_group 0;"); }

// ---------------- 1x1 conv as split-fp16 tensor GEMM (unchanged) ----------------
__global__ void __launch_bounds__(256) conv1x1_tc_kernel(
    const float* __restrict__ X, const float* __restrict__ W,
    const float* __restrict__ bias, float* __restrict__ Cout,
    int OC, int IC)
{
    __shared__ __align__(16) __half Wh[64 * CSTR];
    __shared__ __align__(16) __half Wl[64 * CSTR];
    __shared__ __align__(16) __half Xh[64 * CSTR];
    __shared__ __align__(16) __half Xl[64 * CSTR];

    const int t    = threadIdx.x;
    const int lane = t & 31;
    const int wid  = t >> 5;
    const int o0w  = (wid & 3) * 16;
    const int n0w  = (wid >> 2) * 32;
    const int r    = lane >> 2;
    const int cc   = lane & 3;

    const int n0 = blockIdx.x * 64;
    const int o0 = blockIdx.y * 64;
    const int b  = blockIdx.z;

    const float* Xb = X + ((size_t)b * IC) * NSP + n0;

    const int nX = t & 63;
    const int cg = (t >> 6) * 4;

    float sacc[4][4];
#pragma unroll
    for (int nt = 0; nt < 4; ++nt)
#pragma unroll
        for (int e = 0; e < 4; ++e) sacc[nt][e] = 0.f;

    for (int c0 = 0; c0 < IC; c0 += 32) {
#pragma unroll
        for (int e = 0; e < 2; ++e) {
            int idx = t + e * 256;
            int o  = idx >> 3;
            int c4 = (idx & 7) * 4;
            float4 f = *(const float4*)(W + (size_t)(o0 + o) * IC + c0 + c4);
            uint2 hi, lo;
            split4(f, hi, lo);
            *(uint2*)&Wh[o * CSTR + c4] = hi;
            *(uint2*)&Wl[o * CSTR + c4] = lo;
        }
#pragma unroll
        for (int e = 0; e < 2; ++e) {
            int c = cg + e * 16;
            float4 f;
            f.x = Xb[(size_t)(c0 + c + 0) * NSP + nX];
            f.y = Xb[(size_t)(c0 + c + 1) * NSP + nX];
            f.z = Xb[(size_t)(c0 + c + 2) * NSP + nX];
            f.w = Xb[(size_t)(c0 + c + 3) * NSP + nX];
            uint2 hi, lo;
            split4(f, hi, lo);
            *(uint2*)&Xh[nX * CSTR + c] = hi;
            *(uint2*)&Xl[nX * CSTR + c] = lo;
        }
        __syncthreads();

#pragma unroll
        for (int ks = 0; ks < 2; ++ks) {
            const int arow = (o0w + (lane & 15)) * CSTR + ks * 16 + ((lane >> 4) << 3);
            uint32_t ah0, ah1, ah2, ah3, al0, al1, al2, al3;
            ldsm_x4(ah0, ah1, ah2, ah3, &Wh[arow]);
            ldsm_x4(al0, al1, al2, al3, &Wl[arow]);
#pragma unroll
            for (int p = 0; p < 2; ++p) {
                const int brow = (n0w + p * 16 + ((lane >> 4) << 3) + (lane & 7)) * CSTR
                               + ks * 16 + (lane & 8);
                uint32_t bh0, bh1, bh2, bh3, bl0, bl1, bl2, bl3;
                ldsm_x4(bh0, bh1, bh2, bh3, &Xh[brow]);
                ldsm_x4(bl0, bl1, bl2, bl3, &Xl[brow]);
                mma16816(sacc[2 * p],     ah0, ah1, ah2, ah3, bh0, bh1);
                mma16816(sacc[2 * p + 1], ah0, ah1, ah2, ah3, bh2, bh3);
                mma16816(sacc[2 * p],     ah0, ah1, ah2, ah3, bl0, bl1);
                mma16816(sacc[2 * p + 1], ah0, ah1, ah2, ah3, bl2, bl3);
                mma16816(sacc[2 * p],     al0, al1, al2, al3, bh0, bh1);
                mma16816(sacc[2 * p + 1], al0, al1, al2, al3, bh2, bh3);
            }
        }
        __syncthreads();
    }

    const int o_lo = o0 + o0w + r;
    const int o_hi = o_lo + 8;
    const float blo = bias[o_lo];
    const float bhi = bias[o_hi];
    float* out_lo = Cout + ((size_t)b * OC + o_lo) * NSP + n0 + n0w;
    float* out_hi = Cout + ((size_t)b * OC + o_hi) * NSP + n0 + n0w;
#pragma unroll
    for (int nt = 0; nt < 4; ++nt) {
        int n = nt * 8 + 2 * cc;
        *(float2*)(out_lo + n) = make_float2(sacc[nt][0] + blo, sacc[nt][1] + blo);
        *(float2*)(out_hi + n) = make_float2(sacc[nt][2] + bhi, sacc[nt][3] + bhi);
    }
}

// ---------------- 3x3 depthwise conv; v channels emitted as fp16 ----------------
__global__ void __launch_bounds__(256) dwconv_kernel(
    const float* __restrict__ in, const float* __restrict__ wdw,
    const float* __restrict__ bias, float* __restrict__ out, __half* __restrict__ vh)
{
    const int bc = blockIdx.x;
    const int ch = bc % C3;
    const int b  = bc / C3;
    const float* p = in + (size_t)bc * NSP;

    float w9[9];
#pragma unroll
    for (int i = 0; i < 9; ++i) w9[i] = wdw[ch * 9 + i];

    const int idx = blockIdx.y * 256 + threadIdx.x;
    const int y = idx >> 6;
    const int x = idx & 63;

    float acc = bias[ch];
#pragma unroll
    for (int dy = -1; dy <= 1; ++dy) {
        int yy = y + dy;
        if (yy < 0 || yy > 63) continue;
#pragma unroll
        for (int dx = -1; dx <= 1; ++dx) {
            int xx = x + dx;
            if (xx < 0 || xx > 63) continue;
            acc += __ldg(p + yy * 64 + xx) * w9[(dy + 1) * 3 + (dx + 1)];
        }
    }
    if (ch < 2 * CH) {
        out[(size_t)bc * NSP + idx] = acc;
    } else {
        vh[((size_t)b * CH + (ch - 2 * CH)) * NSP + idx] = __float2half(acc);
    }
}

// ---------------- L2 norm -> fp16 [bh][n][48] (q scaled by T*log2e) ----------------
__global__ void __launch_bounds__(256) norm_kernel(
    const float* __restrict__ qkv, __half* __restrict__ qh, __half* __restrict__ kh,
    const float* __restrict__ temp)
{
    const int bh   = blockIdx.x;
    const int b    = bh >> 2;
    const int head = bh & 3;
    const int n    = blockIdx.y * 256 + threadIdx.x;

    const float* qp = qkv + ((size_t)(b * C3) + head * HD) * NSP + n;
    const float* kp = qp + (size_t)CH * NSP;

    float sq = 0.f, sk = 0.f;
#pragma unroll 16
    for (int d = 0; d < HD; ++d) {
        float qv = qp[(size_t)d * NSP]; sq += qv * qv;
        float kv = kp[(size_t)d * NSP]; sk += kv * kv;
    }
    const float qs = (temp[head] * L2E) / fmaxf(sqrtf(sq), 1e-12f);
    const float ks = 1.0f / fmaxf(sqrtf(sk), 1e-12f);

    __half* qo = qh + ((size_t)bh * NSP + n) * HD;
    __half* ko = kh + ((size_t)bh * NSP + n) * HD;
#pragma unroll
    for (int g = 0; g < 6; ++g) {
        float q0 = qp[(size_t)(g * 8 + 0) * NSP] * qs, q1 = qp[(size_t)(g * 8 + 1) * NSP] * qs;
        float q2 = qp[(size_t)(g * 8 + 2) * NSP] * qs, q3 = qp[(size_t)(g * 8 + 3) * NSP] * qs;
        float q4 = qp[(size_t)(g * 8 + 4) * NSP] * qs, q5 = qp[(size_t)(g * 8 + 5) * NSP] * qs;
        float q6 = qp[(size_t)(g * 8 + 6) * NSP] * qs, q7 = qp[(size_t)(g * 8 + 7) * NSP] * qs;
        *(uint4*)(qo + g * 8) = make_uint4(cvt2(q1, q0), cvt2(q3, q2), cvt2(q5, q4), cvt2(q7, q6));
        float k0 = kp[(size_t)(g * 8 + 0) * NSP] * ks, k1 = kp[(size_t)(g * 8 + 1) * NSP] * ks;
        float k2 = kp[(size_t)(g * 8 + 2) * NSP] * ks, k3 = kp[(size_t)(g * 8 + 3) * NSP] * ks;
        float k4 = kp[(size_t)(g * 8 + 4) * NSP] * ks, k5 = kp[(size_t)(g * 8 + 5) * NSP] * ks;
        float k6 = kp[(size_t)(g * 8 + 6) * NSP] * ks, k7 = kp[(size_t)(g * 8 + 7) * NSP] * ks;
        *(uint4*)(ko + g * 8) = make_uint4(cvt2(k1, k0), cvt2(k3, k2), cvt2(k5, k4), cvt2(k7, k6));
    }
}

// ---------------- flash attention: BQ=128, Q in registers, no cross-warp reduce --------
// grid: (NSP/128, B2*HEADS), block 256 (8 warps, warp w owns query rows [16w, 16w+16))
__global__ void __launch_bounds__(256) attn_kernel(
    const __half* __restrict__ qh, const __half* __restrict__ kh,
    const __half* __restrict__ vh, const float* __restrict__ temp,
    float* __restrict__ out)
{
    __shared__ __align__(16) __half Qs[128 * QKSTR];   // 14.0 KB
    __shared__ __align__(16) __half Ks[2][64 * QKSTR]; // 14.0 KB
    __shared__ __align__(16) __half Vs[2][HD * VSTR];  // 13.5 KB

    const int t    = threadIdx.x;
    const int lane = t & 31;
    const int wid  = t >> 5;
    const int i0   = wid * 16;
    const int r    = lane >> 2;
    const int cc   = lane & 3;

    const int bh   = blockIdx.y;
    const int b    = bh >> 2;
    const int head = bh & 3;
    const int n0   = blockIdx.x * 128;

    const __half* qb = qh + (size_t)bh * NSP * HD;
    const __half* kb = kh + (size_t)bh * NSP * HD;
    const __half* vb = vh + ((size_t)b * CH + head * HD) * NSP;
    const float   cbias = fabsf(temp[head]) * L2E;

    // ---- prologue: cp.async Q (768 chunks) + K0 (384) + V0 (384) ----
#pragma unroll
    for (int e = 0; e < 3; ++e) {
        int ch = t + e * 256, row = ch / 6, c = (ch % 6) * 8;
        cp16(&Qs[row * QKSTR + c], qb + ((size_t)(n0 + row)) * HD + c);
    }
    {
        int row = t / 6, c = (t % 6) * 8;
        cp16(&Ks[0][row * QKSTR + c], kb + (size_t)row * HD + c);
    }
    if (t < 128) {
        int ch = t + 256, row = ch / 6, c = (ch % 6) * 8;
        cp16(&Ks[0][row * QKSTR + c], kb + (size_t)row * HD + c);
    }
    {
        int row = t >> 3, c = (t & 7) * 8;
        cp16(&Vs[0][row * VSTR + c], vb + (size_t)row * NSP + c);
    }
    if (t < 128) {
        int ch = t + 256, row = ch >> 3, c = (ch & 7) * 8;
        cp16(&Vs[0][row * VSTR + c], vb + (size_t)row * NSP + c);
    }
    cp_commit();

    float oacc[6][4];
#pragma unroll
    for (int nt = 0; nt < 6; ++nt)
#pragma unroll
        for (int e = 0; e < 4; ++e) oacc[nt][e] = 0.f;
    float l_lo = 0.f, l_hi = 0.f;

    uint32_t qa[3][4];   // Q fragments, loaded once

    // per-thread prefetch coords
    const int krow0 = t / 6,          kc0 = (t % 6) * 8;
    const int krow1 = (t + 256) / 6,  kc1 = ((t + 256) % 6) * 8;
    const int vrow0 = t >> 3,         vc0 = (t & 7) * 8;
    const int vrow1 = (t + 256) >> 3, vc1 = ((t + 256) & 7) * 8;

    for (int it = 0; it < NSP / 64; ++it) {
        const int cur = it & 1;
        const __half* Kc = Ks[cur];
        const __half* Vc = Vs[cur];
        const bool has_next = (it < NSP / 64 - 1);

        cp_wait0();
        __syncthreads();

        if (it == 0) {
#pragma unroll
            for (int ks = 0; ks < 3; ++ks)
                ldsm_x4(qa[ks][0], qa[ks][1], qa[ks][2], qa[ks][3],
                        &Qs[(i0 + (lane & 15)) * QKSTR + ks * 16 + ((lane >> 4) << 3)]);
        }

        if (has_next) {
            const int nb = cur ^ 1;
            const int m0n = (it + 1) * 64;
            cp16(&Ks[nb][krow0 * QKSTR + kc0], kb + ((size_t)(m0n + krow0)) * HD + kc0);
            if (t < 128)
                cp16(&Ks[nb][krow1 * QKSTR + kc1], kb + ((size_t)(m0n + krow1)) * HD + kc1);
            cp16(&Vs[nb][vrow0 * VSTR + vc0], vb + (size_t)vrow0 * NSP + m0n + vc0);
            if (t < 128)
                cp16(&Vs[nb][vrow1 * VSTR + vc1], vb + (size_t)vrow1 * NSP + m0n + vc1);
            cp_commit();
        }

        // ---- S = Q K^T (warp: 16i x 64j) ----
        float sacc[8][4];
#pragma unroll
        for (int nt = 0; nt < 8; ++nt)
#pragma unroll
            for (int e = 0; e < 4; ++e) sacc[nt][e] = 0.f;

#pragma unroll
        for (int ks = 0; ks < 3; ++ks) {
#pragma unroll
            for (int p = 0; p < 4; ++p) {
                uint32_t b0, b1, b2, b3;
                int row = p * 16 + ((lane >> 4) << 3) + (lane & 7);
                int col = ks * 16 + (lane & 8);
                ldsm_x4(b0, b1, b2, b3, &Kc[row * QKSTR + col]);
                mma16816(sacc[2 * p],     qa[ks][0], qa[ks][1], qa[ks][2], qa[ks][3], b0, b1);
                mma16816(sacc[2 * p + 1], qa[ks][0], qa[ks][1], qa[ks][2], qa[ks][3], b2, b3);
            }
        }

        // ---- softmax in registers: P = exp2(S - c) ----
        uint32_t plo[8], phi[8];
        uint32_t sum_lo = 0, sum_hi = 0;
#pragma unroll
        for (int nt = 0; nt < 8; ++nt) {
            plo[nt] = ex2h2(cvt2(sacc[nt][1] - cbias, sacc[nt][0] - cbias));
            phi[nt] = ex2h2(cvt2(sacc[nt][3] - cbias, sacc[nt][2] - cbias));
            sum_lo = hadd2(sum_lo, plo[nt]);
            sum_hi = hadd2(sum_hi, phi[nt]);
        }
        {
            float2 f0 = h22f2(sum_lo); l_lo += f0.x + f0.y;
            float2 f1 = h22f2(sum_hi); l_hi += f1.x + f1.y;
        }

        // ---- O += P V^T (warp: 16i x 48d over k=64) ----
#pragma unroll
        for (int nt = 0; nt < 6; ++nt) {
#pragma unroll
            for (int h = 0; h < 2; ++h) {
                uint32_t b0, b1, b2, b3;
                ldsm_x4(b0, b1, b2, b3,
                        &Vc[(nt * 8 + (lane & 7)) * VSTR + h * 32 + ((lane >> 3) & 3) * 8]);
                mma16816(oacc[nt], plo[4 * h + 0], phi[4 * h + 0],
                                   plo[4 * h + 1], phi[4 * h + 1], b0, b1);
                mma16816(oacc[nt], plo[4 * h + 2], phi[4 * h + 2],
                                   plo[4 * h + 3], phi[4 * h + 3], b2, b3);
            }
        }
        __syncthreads();
    }

    // ---- epilogue: per-warp, no cross-warp reduce ----
    l_lo += __shfl_xor_sync(0xffffffffu, l_lo, 1);
    l_lo += __shfl_xor_sync(0xffffffffu, l_lo, 2);
    l_hi += __shfl_xor_sync(0xffffffffu, l_hi, 1);
    l_hi += __shfl_xor_sync(0xffffffffu, l_hi, 2);
    const float linv_lo = 1.f / l_lo;
    const float linv_hi = 1.f / l_hi;
    float* ob = out + ((size_t)(b * CH) + head * HD) * NSP + n0;
#pragma unroll
    for (int nt = 0; nt < 6; ++nt) {
        int d = nt * 8 + 2 * cc;
        ob[(size_t)d * NSP + i0 + r]           = oacc[nt][0] * linv_lo;
        ob[(size_t)(d + 1) * NSP + i0 + r]     = oacc[nt][1] * linv_lo;
        ob[(size_t)d * NSP + i0 + r + 8]       = oacc[nt][2] * linv_hi;
        ob[(size_t)(d + 1) * NSP + i0 + r + 8] = oacc[nt][3] * linv_hi;
    }
}

// ---------------- launcher ----------------
extern "C" void kernel_launch(void* const* d_in, const int* in_sizes, int n_in,
                              void* d_out, int out_size)
{
    const float* x      = (const float*)d_in[0];
    const float* w_qkv  = (const float*)d_in[1];
    const float* b_qkv  = (const float*)d_in[2];
    const float* w_dw   = (const float*)d_in[3];
    const float* b_dw   = (const float*)d_in[4];
    const float* w_proj = (const float*)d_in[5];
    const float* b_proj = (const float*)d_in[6];
    const float* temp   = (const float*)d_in[7];
    float* out = (float*)d_out;

    float*  qkv1; cudaGetSymbolAddress((void**)&qkv1, g_qkv);
    float*  qkv2; cudaGetSymbolAddress((void**)&qkv2, g_qkv2);
    float*  att;  cudaGetSymbolAddress((void**)&att,  g_att);
    __half* qhp;  cudaGetSymbolAddress((void**)&qhp,  g_qh);
    __half* khp;  cudaGetSymbolAddress((void**)&khp,  g_kh);
    __half* vhp;  cudaGetSymbolAddress((void**)&vhp,  g_vh);

    conv1x1_tc_kernel<<<dim3(NSP / 64, C3 / 64, B2), 256>>>(x, w_qkv, b_qkv, qkv1, C3, CH);
    dwconv_kernel<<<dim3(B2 * C3, NSP / 256), 256>>>(qkv1, w_dw, b_dw, qkv2, vhp);
    norm_kernel<<<dim3(B2 * HEADS, NSP / 256), 256>>>(qkv2, qhp, khp, temp);
    attn_kernel<<<dim3(NSP / 128, B2 * HEADS), 256>>>(qhp, khp, vhp, temp, att);
    conv1x1_tc_kernel<<<dim3(NSP / 64, CH / 64, B2), 256>>>(att, w_proj, b_proj, out, CH, CH);
}